// round 8
// baseline (speedup 1.0000x reference)
#include <cuda_runtime.h>
#include <cstdint>
#include <cstddef>

// Problem constants (fixed shapes)
#define Tn    1024
#define Bn    128
#define In    64
#define Hn    256
#define Cn    64
#define OUTL  128
#define KT    320            // In + Hn
#define NCTA  128
#define NTHR  256
#define CLS   8              // cluster size (CTAs) == batch rows per cluster
#define RB    8              // rows per cluster
#define GC    128            // gate-cols per CTA (of 4*Hn=1024)
#define HCPC  32             // h-cols per CTA (GC/4)
#define ASTR  328            // activation row stride (floats), 16B-multiple
#define ABUF  (RB * ASTR)    // one activation buffer (floats)
#define KSL   160            // K-slice per k-half thread group

typedef unsigned long long ull;

// ---------------- persistent device state ----------------
__device__ float g_decH[Bn][OUTL][Hn];       // decoder hidden states for epilogue MLP

// ---------------- small helpers ----------------
__device__ __forceinline__ uint32_t smem_u32(const void* p) {
    uint32_t a;
    asm("{ .reg .u64 t; cvta.to.shared.u64 t, %1; cvt.u32.u64 %0, t; }"
        : "=r"(a) : "l"(p));
    return a;
}
__device__ __forceinline__ uint32_t ctarank() {
    uint32_t r; asm("mov.u32 %0, %%cluster_ctarank;" : "=r"(r)); return r;
}
__device__ __forceinline__ uint32_t mapa_u32(uint32_t addr, uint32_t rank) {
    uint32_t r;
    asm volatile("mapa.shared::cluster.u32 %0, %1, %2;" : "=r"(r) : "r"(addr), "r"(rank));
    return r;
}
__device__ __forceinline__ void st_cluster_u64(uint32_t addr, ull v) {
    asm volatile("st.shared::cluster.u64 [%0], %1;" :: "r"(addr), "l"(v) : "memory");
}
#define CLUSTER_SYNC() do { \
    asm volatile("barrier.cluster.arrive.aligned;" ::: "memory"); \
    asm volatile("barrier.cluster.wait.aligned;"   ::: "memory"); \
} while (0)

__device__ __forceinline__ ull pk2(float x, float y) {
    ull r; asm("mov.b64 %0, {%1, %2};" : "=l"(r) : "f"(x), "f"(y)); return r;
}
__device__ __forceinline__ void upk2(ull v, float& x, float& y) {
    asm("mov.b64 {%0, %1}, %2;" : "=f"(x), "=f"(y) : "l"(v));
}
__device__ __forceinline__ ull ffma2(ull a, ull b, ull c) {
    ull d; asm("fma.rn.f32x2 %0, %1, %2, %3;" : "=l"(d) : "l"(a), "l"(b), "l"(c));
    return d;
}
__device__ __forceinline__ float sigf(float x) {
    return 1.0f / (1.0f + __expf(-x));
}
__device__ __forceinline__ float tanhf_fast(float x) {
    x = fminf(fmaxf(x, -15.0f), 15.0f);
    float e = __expf(2.0f * x);
    return (e - 1.0f) / (e + 1.0f);
}

// GEMM partial: this thread's gate-col gc, K slice [kbase, kbase+160), 8 rows.
// Weights register-resident (wr2), activations broadcast LDS.128.
// I0 = first k4-unit to process (decoder khalf0 skips the zero x region).
template<int I0>
__device__ __forceinline__ void gemm_part(const float* __restrict__ aCur,
                                          float* __restrict__ part,
                                          const ull* __restrict__ wr2,
                                          int kbase, int gc, int khalf)
{
    #pragma unroll
    for (int r0 = 0; r0 < RB; r0 += 2) {
        const float* p0 = aCur + r0 * ASTR + kbase;
        const float* p1 = p0 + ASTR;
        ull ac0 = 0ull, ac1 = 0ull;
        #pragma unroll 8
        for (int i = I0; i < KSL / 4; ++i) {
            ulonglong2 A0 = *(const ulonglong2*)(p0 + i * 4);
            ac0 = ffma2(A0.x, wr2[2 * i], ac0);
            ac0 = ffma2(A0.y, wr2[2 * i + 1], ac0);
            ulonglong2 A1 = *(const ulonglong2*)(p1 + i * 4);
            ac1 = ffma2(A1.x, wr2[2 * i], ac1);
            ac1 = ffma2(A1.y, wr2[2 * i + 1], ac1);
        }
        float lo, hi;
        upk2(ac0, lo, hi); part[((r0 + 0) * 2 + khalf) * GC + gc] = lo + hi;
        upk2(ac1, lo, hi); part[((r0 + 1) * 2 + khalf) * GC + gc] = lo + hi;
    }
}

// ---------------- persistent clustered encoder + decoder kernel ----------------
extern "C" __global__ void __launch_bounds__(NTHR, 1) __cluster_dims__(CLS, 1, 1)
lstm_persistent(const float* __restrict__ x, const int* __restrict__ lengths,
                const float* __restrict__ W_ih, const float* __restrict__ W_hh,
                const float* __restrict__ b_ih, const float* __restrict__ b_hh)
{
    extern __shared__ float sm[];
    float* aBuf    = sm;                       // [2][RB][ASTR] activations [x_t | h]
    float* part    = sm + 2 * ABUF;            // [RB][2][GC] k-half partials
    float* h2stage = part + RB * 2 * GC;       // [RB][HCPC] own h2 slab staging

    const int      tid   = threadIdx.x;
    const uint32_t rank  = ctarank();
    const int      row0  = (blockIdx.x >> 3) * RB;   // cluster id * 8

    // GEMM role: gate-col + k-half
    const int gc    = tid & (GC - 1);
    const int khalf = tid >> 7;
    const int kbase = khalf * KSL;
    const int grow  = (gc >> 5) * Hn + (int)rank * HCPC + (gc & 31); // global gate row

    // ---- weights into registers (once): 160 floats -> 80 packed b64 ----
    ull wr2[KSL / 2];
    {
        float wv[KSL];
        #pragma unroll
        for (int k = 0; k < KSL; ++k) {
            int kk = kbase + k;
            wv[k] = (kk < In) ? W_ih[(size_t)grow * In + kk]
                              : W_hh[(size_t)grow * Hn + (kk - In)];
        }
        #pragma unroll
        for (int i = 0; i < KSL / 2; ++i) wr2[i] = pk2(wv[2 * i], wv[2 * i + 1]);
    }

    // update role: thread owns (row ur, local h-col uc)
    const int ur = tid >> 5, uc = tid & 31;
    float bq0, bq1, bq2, bq3;
    {
        int c = (int)rank * HCPC + uc;
        bq0 = b_ih[0 * Hn + c] + b_hh[0 * Hn + c];
        bq1 = b_ih[1 * Hn + c] + b_hh[1 * Hn + c];
        bq2 = b_ih[2 * Hn + c] + b_hh[2 * Hn + c];
        bq3 = b_ih[3 * Hn + c] + b_hh[3 * Hn + c];
    }
    const int ulen = lengths[row0 + ur];
    float creg = 0.0f;

    // ---- init: zero h region of buffer 0, stage x_0 into buffer 0 ----
    for (int idx = tid; idx < RB * (Hn / 4); idx += NTHR) {      // 8*64 float4
        int r = idx >> 6, c4 = idx & 63;
        *(((float4*)(aBuf + r * ASTR + In)) + c4) = make_float4(0.f, 0.f, 0.f, 0.f);
    }
    if (tid < RB * (In / 4)) {                                    // 8*16 float4
        int r = tid >> 4, c4 = tid & 15;
        *(((float4*)(aBuf + r * ASTR)) + c4) =
            *(((const float4*)(x + ((size_t)(row0 + r) * Tn) * In)) + c4);
    }
    __syncthreads();
    CLUSTER_SYNC();                   // all cluster smem initialized

    // DSMEM push constants: this thread pushes 4 ull of the 128-ull slab to rank dr
    const uint32_t dr  = (uint32_t)(tid >> 5);        // destination rank 0..7
    const uint32_t hsA = smem_u32(h2stage);
    const uint32_t aA  = smem_u32(aBuf);
    const int      slabColOff = In + (int)rank * HCPC; // peer a[.] col offset (floats)

    int p = 0;

    // ================= encoder: 1024 steps =================
    for (int t = 0; t < Tn; ++t) {
        const float* aCur = aBuf + p * ABUF;
        float*       aNxt = aBuf + (p ^ 1) * ABUF;

        gemm_part<0>(aCur, part, wr2, kbase, gc, khalf);
        __syncthreads();

        // reduce 2 k-half partials + bias; cell update for (ur, uc)
        {
            const float* pr0 = part + (ur * 2 + 0) * GC + uc;
            const float* pr1 = part + (ur * 2 + 1) * GC + uc;
            float g0 = bq0 + pr0[0]   + pr1[0];
            float g1 = bq1 + pr0[32]  + pr1[32];
            float g2 = bq2 + pr0[64]  + pr1[64];
            float g3 = bq3 + pr0[96]  + pr1[96];
            float c2 = sigf(g1) * creg + sigf(g0) * tanhf_fast(g2);
            float h2 = sigf(g3) * tanhf_fast(c2);
            if (t >= ulen) {                         // length mask: freeze state
                h2 = aCur[ur * ASTR + slabColOff + uc];
                c2 = creg;
            }
            creg = c2;
            h2stage[ur * HCPC + uc] = h2;
        }
        // stage x_{t+1} into next buffer (disjoint from peers' slab writes)
        if (t + 1 < Tn && tid < RB * (In / 4)) {
            int r = tid >> 4, c4 = tid & 15;
            *(((float4*)(aNxt + r * ASTR)) + c4) =
                *(((const float4*)(x + ((size_t)(row0 + r) * Tn + t + 1) * In)) + c4);
        }
        __syncthreads();

        // push own slab (8 rows x 32 cols) into every cluster CTA's next buffer
        {
            uint32_t aNxtA = aA + (uint32_t)((p ^ 1) * ABUF) * 4u;
            #pragma unroll
            for (int j = 0; j < 4; ++j) {
                int u   = (tid & 31) + j * 32;        // ull index 0..127
                int row = u >> 4, cp = u & 15;
                ull v = *((const ull*)h2stage + u);
                uint32_t la = aNxtA + (uint32_t)(row * ASTR + slabColOff + cp * 2) * 4u;
                st_cluster_u64(mapa_u32(la, dr), v);
            }
        }
        CLUSTER_SYNC();
        p ^= 1;
    }

    // ================= decoder: 128 steps (gates_x = bias; x-K skipped) ======
    for (int s = 0; s < OUTL; ++s) {
        const float* aCur = aBuf + p * ABUF;

        if (khalf == 0) gemm_part<In / 4>(aCur, part, wr2, kbase, gc, khalf);
        else            gemm_part<0>(aCur, part, wr2, kbase, gc, khalf);
        __syncthreads();

        {
            const float* pr0 = part + (ur * 2 + 0) * GC + uc;
            const float* pr1 = part + (ur * 2 + 1) * GC + uc;
            float g0 = bq0 + pr0[0]   + pr1[0];
            float g1 = bq1 + pr0[32]  + pr1[32];
            float g2 = bq2 + pr0[64]  + pr1[64];
            float g3 = bq3 + pr0[96]  + pr1[96];
            float c2 = sigf(g1) * creg + sigf(g0) * tanhf_fast(g2);
            float h2 = sigf(g3) * tanhf_fast(c2);
            creg = c2;
            h2stage[ur * HCPC + uc] = h2;
            g_decH[row0 + ur][s][(int)rank * HCPC + uc] = h2;   // for epilogue MLP
        }
        __syncthreads();

        {
            uint32_t aNxtA = aA + (uint32_t)((p ^ 1) * ABUF) * 4u;
            #pragma unroll
            for (int j = 0; j < 4; ++j) {
                int u   = (tid & 31) + j * 32;
                int row = u >> 4, cp = u & 15;
                ull v = *((const ull*)h2stage + u);
                uint32_t la = aNxtA + (uint32_t)(row * ASTR + slabColOff + cp * 2) * 4u;
                st_cluster_u64(mapa_u32(la, dr), v);
            }
        }
        CLUSTER_SYNC();
        p ^= 1;
    }
}

// ---------------- epilogue: out = relu(decH @ W1^T + b1) @ W2^T + b2 ----------------
// M = Bn*OUTL = 16384 rows, 32 rows per CTA -> 512 CTAs, fully parallel.
extern "C" __global__ void __launch_bounds__(256, 1)
mlp_epilogue(const float* __restrict__ W1, const float* __restrict__ b1,
             const float* __restrict__ W2, const float* __restrict__ b2,
             float* __restrict__ out)
{
    extern __shared__ float sm[];
    float* As = sm;            // [32][256] decoder h tile
    float* Hs = sm + 32 * 256; // [32][256] relu hidden tile

    const int tid  = threadIdx.x;
    const int lane = tid & 31;
    const int w    = tid >> 5;
    const int m0   = blockIdx.x * 32;

    const float* dh = &g_decH[0][0][0];   // flat: row m = b*OUTL + s, stride Hn
    for (int idx = tid; idx < 32 * (Hn / 4); idx += 256) {
        int r = idx >> 6, c4 = idx & 63;
        *(((float4*)(As + r * Hn)) + c4) =
            *(((const float4*)(dh + (size_t)(m0 + r) * Hn)) + c4);
    }
    __syncthreads();

    // hidden phase: warp w owns hidden cols [w*32, w*32+32), lane -> one col
    {
        const int h = w * 32 + lane;
        float acc[32];
        const float bv = b1[h];
        #pragma unroll
        for (int r = 0; r < 32; ++r) acc[r] = bv;
        for (int k = 0; k < Hn; k += 4) {
            float4 wv = *(const float4*)(W1 + (size_t)h * Hn + k);
            #pragma unroll
            for (int r = 0; r < 32; ++r) {
                float4 av = *(const float4*)(As + r * Hn + k);
                acc[r] = fmaf(av.x, wv.x, fmaf(av.y, wv.y,
                         fmaf(av.z, wv.z, fmaf(av.w, wv.w, acc[r]))));
            }
        }
        #pragma unroll
        for (int r = 0; r < 32; ++r) Hs[r * Hn + h] = fmaxf(acc[r], 0.0f);
    }
    __syncthreads();

    // out phase: warp w owns rows w*4..w*4+3; lane -> out cols {lane, lane+32}
    {
        float o[4][2];
        const float ba = b2[lane];
        const float bb = b2[lane + 32];
        #pragma unroll
        for (int ri = 0; ri < 4; ++ri) { o[ri][0] = ba; o[ri][1] = bb; }
        for (int k = 0; k < Hn; k += 4) {
            float4 wa = *(const float4*)(W2 + (size_t)lane * Hn + k);
            float4 wb = *(const float4*)(W2 + (size_t)(lane + 32) * Hn + k);
            #pragma unroll
            for (int ri = 0; ri < 4; ++ri) {
                float4 hv = *(const float4*)(Hs + (w * 4 + ri) * Hn + k);
                o[ri][0] = fmaf(hv.x, wa.x, fmaf(hv.y, wa.y,
                           fmaf(hv.z, wa.z, fmaf(hv.w, wa.w, o[ri][0]))));
                o[ri][1] = fmaf(hv.x, wb.x, fmaf(hv.y, wb.y,
                           fmaf(hv.z, wb.z, fmaf(hv.w, wb.w, o[ri][1]))));
            }
        }
        #pragma unroll
        for (int ri = 0; ri < 4; ++ri) {
            size_t m = (size_t)(m0 + w * 4 + ri);
            out[m * Cn + lane]      = o[ri][0];
            out[m * Cn + lane + 32] = o[ri][1];
        }
    }
}

// ---------------- launch ----------------
extern "C" void kernel_launch(void* const* d_in, const int* in_sizes, int n_in,
                              void* d_out, int out_size) {
    // input order: x, lengths, [out_lengths], W_ih, W_hh, b_ih, b_hh, W1, b1, W2, b2
    const int off = (n_in >= 11) ? 3 : 2;
    const float* x       = (const float*)d_in[0];
    const int*   lengths = (const int*)  d_in[1];
    const float* W_ih    = (const float*)d_in[off + 0];
    const float* W_hh    = (const float*)d_in[off + 1];
    const float* b_ih    = (const float*)d_in[off + 2];
    const float* b_hh    = (const float*)d_in[off + 3];
    const float* W1      = (const float*)d_in[off + 4];
    const float* b1      = (const float*)d_in[off + 5];
    const float* W2      = (const float*)d_in[off + 6];
    const float* b2      = (const float*)d_in[off + 7];
    float*       out     = (float*)d_out;

    const size_t smem1 = (size_t)(2 * ABUF + RB * 2 * GC + RB * HCPC) * sizeof(float)
                       + 128;                                        // ~30.4 KB
    const size_t smem2 = (size_t)2 * 32 * Hn * sizeof(float);        // 64 KB

    cudaFuncSetAttribute(lstm_persistent,
                         cudaFuncAttributeMaxDynamicSharedMemorySize, (int)smem1);
    cudaFuncSetAttribute(mlp_epilogue,
                         cudaFuncAttributeMaxDynamicSharedMemorySize, (int)smem2);

    lstm_persistent<<<NCTA, NTHR, smem1>>>(x, lengths, W_ih, W_hh, b_ih, b_hh);
    mlp_epilogue<<<(Bn * OUTL) / 32, 256, smem2>>>(W1, b1, W2, b2, out);
}

// round 9
// speedup vs baseline: 4.9859x; 4.9859x over previous
#include <cuda_runtime.h>
#include <cstdint>
#include <cstddef>

// Problem constants (fixed shapes)
#define Tn    1024
#define Bn    128
#define In    64
#define Hn    256
#define Cn    64
#define OUTL  128
#define KT    320            // In + Hn
#define NCTA  128
#define NTHR  256
#define GRP   8              // CTAs per exchange group
#define NGRP  16             // 128/8
#define RB    8              // batch rows per group
#define GC    128            // gate-cols per CTA
#define HCPC  32             // h-cols per CTA
#define KQ    80             // K per quarter-slice (4 x 80 = 320)
#define ASTR  328            // activation row stride (floats), 16B multiple

typedef unsigned long long ull;

// ---------------- persistent device state ----------------
__device__ float g_h[2][NGRP][RB][Hn];       // double-buffered hidden state
__device__ float g_decH[Bn][OUTL][Hn];       // decoder hidden states for epilogue

struct alignas(128) PadCtr { unsigned v; unsigned pad[31]; };
__device__ PadCtr g_arrive[NGRP];
__device__ PadCtr g_phase[NGRP];

// ---------------- helpers ----------------
__device__ __forceinline__ unsigned ld_acq_u32(const unsigned* p) {
    unsigned v;
    asm volatile("ld.acquire.gpu.u32 %0, [%1];" : "=r"(v) : "l"(p) : "memory");
    return v;
}
__device__ __forceinline__ ull pk2(float x, float y) {
    ull r; asm("mov.b64 %0, {%1, %2};" : "=l"(r) : "f"(x), "f"(y)); return r;
}
__device__ __forceinline__ void upk2(ull v, float& x, float& y) {
    asm("mov.b64 {%0, %1}, %2;" : "=f"(x), "=f"(y) : "l"(v));
}
__device__ __forceinline__ ull ffma2(ull a, ull b, ull c) {
    ull d; asm("fma.rn.f32x2 %0, %1, %2, %3;" : "=l"(d) : "l"(a), "l"(b), "l"(c));
    return d;
}
__device__ __forceinline__ float sigf(float x) {
    return 1.0f / (1.0f + __expf(-x));
}
__device__ __forceinline__ float tanhf_fast(float x) {
    x = fminf(fmaxf(x, -15.0f), 15.0f);
    float e = __expf(2.0f * x);
    return (e - 1.0f) / (e + 1.0f);
}

// GEMM partial: thread owns 2 gate-cols (c0,c1) and K-quarter kq, all 8 rows.
// Activations via broadcast LDS.128 (1 load -> 4 FFMA2). Weights in regs.
// U0 = first 4-k unit (decoder kq0 skips the zeroed x region).
template<int U0>
__device__ __forceinline__ void gemm_part(const float* __restrict__ aS,
                                          float* __restrict__ part,
                                          const ull* __restrict__ wr,
                                          int kbase, int kq, int cp)
{
    #pragma unroll 1
    for (int r0 = 0; r0 < RB; r0 += 2) {
        const float* p0 = aS + r0 * ASTR + kbase;
        const float* p1 = p0 + ASTR;
        ull a00 = 0ull, a01 = 0ull, a10 = 0ull, a11 = 0ull;
        #pragma unroll
        for (int u = U0; u < KQ / 4; ++u) {          // up to 20 units of 4 k
            ulonglong2 A0 = *(const ulonglong2*)(p0 + u * 4);
            a00 = ffma2(A0.x, wr[4 * u + 0], a00);
            a00 = ffma2(A0.y, wr[4 * u + 1], a00);
            a01 = ffma2(A0.x, wr[4 * u + 2], a01);
            a01 = ffma2(A0.y, wr[4 * u + 3], a01);
            ulonglong2 A1 = *(const ulonglong2*)(p1 + u * 4);
            a10 = ffma2(A1.x, wr[4 * u + 0], a10);
            a10 = ffma2(A1.y, wr[4 * u + 1], a10);
            a11 = ffma2(A1.x, wr[4 * u + 2], a11);
            a11 = ffma2(A1.y, wr[4 * u + 3], a11);
        }
        float lo, hi, s00, s01, s10, s11;
        upk2(a00, lo, hi); s00 = lo + hi;
        upk2(a01, lo, hi); s01 = lo + hi;
        upk2(a10, lo, hi); s10 = lo + hi;
        upk2(a11, lo, hi); s11 = lo + hi;
        // float2 stores: conflict-free (consecutive 8B per lane)
        *(float2*)(part + ((r0 + 0) * 4 + kq) * GC + 2 * cp) = make_float2(s00, s01);
        *(float2*)(part + ((r0 + 1) * 4 + kq) * GC + 2 * cp) = make_float2(s10, s11);
    }
}

// ---------------- persistent encoder + decoder kernel ----------------
extern "C" __global__ void __launch_bounds__(NTHR, 1)
lstm_persistent(const float* __restrict__ x, const int* __restrict__ lengths,
                const float* __restrict__ W_ih, const float* __restrict__ W_hh,
                const float* __restrict__ b_ih, const float* __restrict__ b_hh)
{
    extern __shared__ float sm[];
    float* aS   = sm;                  // [RB][ASTR] activations [x_t | h]
    float* part = sm + RB * ASTR;      // [RB][4][GC] K-quarter partials

    const int tid  = threadIdx.x;
    const int grp  = blockIdx.x >> 3;  // group 0..15
    const int rank = blockIdx.x & 7;   // rank in group 0..7
    const int row0 = grp * RB;

    // GEMM role: col-pair + K-quarter
    const int cp    = tid & 63;        // col pair 0..63
    const int kq    = tid >> 6;        // K quarter 0..3
    const int kbase = kq * KQ;
    const int c0    = cp * 2, c1 = cp * 2 + 1;

    // ---- weights into registers (once): 2 cols x 80 K = 160 floats = 80 b64 ----
    ull wr[KQ];                                   // 80 packed pairs
    {
        const int grow0 = (c0 >> 5) * Hn + rank * HCPC + (c0 & 31);
        const int grow1 = (c1 >> 5) * Hn + rank * HCPC + (c1 & 31);
        #pragma unroll
        for (int u = 0; u < KQ / 4; ++u) {
            float w0[4], w1[4];
            #pragma unroll
            for (int j = 0; j < 4; ++j) {
                int kk = kbase + u * 4 + j;
                w0[j] = (kk < In) ? W_ih[(size_t)grow0 * In + kk]
                                  : W_hh[(size_t)grow0 * Hn + (kk - In)];
                w1[j] = (kk < In) ? W_ih[(size_t)grow1 * In + kk]
                                  : W_hh[(size_t)grow1 * Hn + (kk - In)];
            }
            wr[4 * u + 0] = pk2(w0[0], w0[1]);
            wr[4 * u + 1] = pk2(w0[2], w0[3]);
            wr[4 * u + 2] = pk2(w1[0], w1[1]);
            wr[4 * u + 3] = pk2(w1[2], w1[3]);
        }
    }

    // update role: thread owns (row ur, local h-col uc)
    const int ur = tid >> 5, uc = tid & 31;
    float bq0, bq1, bq2, bq3;
    {
        int c = rank * HCPC + uc;
        bq0 = b_ih[0 * Hn + c] + b_hh[0 * Hn + c];
        bq1 = b_ih[1 * Hn + c] + b_hh[1 * Hn + c];
        bq2 = b_ih[2 * Hn + c] + b_hh[2 * Hn + c];
        bq3 = b_ih[3 * Hn + c] + b_hh[3 * Hn + c];
    }
    const int ulen = lengths[row0 + ur];
    float creg = 0.0f;

    // ---- init: zero own h0 slab in global, stage x_0 into smem ----
    unsigned base = 0;
    if (tid == 0) base = ld_acq_u32(&g_phase[grp].v);  // before our arrival: stable
    if (tid < 64) {                                    // 8 rows x 8 float4 = 32 cols
        int r = tid >> 3, c4 = tid & 7;
        *(((float4*)&g_h[0][grp][r][rank * HCPC]) + c4) = make_float4(0.f, 0.f, 0.f, 0.f);
    }
    if (tid < RB * (In / 4)) {                         // 8 x 16 float4
        int r = tid >> 4, c4 = tid & 15;
        *(((float4*)(aS + r * ASTR)) + c4) =
            *(((const float4*)(x + ((size_t)(row0 + r) * Tn) * In)) + c4);
    }
    __syncthreads();
    unsigned nb = 1;
    if (tid == 0) {
        __threadfence();
        unsigned old = atomicAdd(&g_arrive[grp].v, 1u);
        if ((old & 7u) == 7u)
            asm volatile("red.release.gpu.global.add.u32 [%0], %1;"
                         :: "l"(&g_phase[grp].v), "r"(1u) : "memory");
        else
            while ((int)(ld_acq_u32(&g_phase[grp].v) - (base + nb)) < 0) { }
    }
    __syncthreads();
    ++nb;

    int p = 0;

    // ================= encoder: 1024 steps =================
    for (int t = 0; t < Tn; ++t) {
        // stage h (L2-only: peers wrote it last step)
        {
            int idx = tid;                 // 512 float4 over 256 threads
            #pragma unroll
            for (int it = 0; it < 2; ++it) {
                int r = idx >> 6, c4 = idx & 63;
                float4 v = __ldcg(((const float4*)&g_h[p][grp][r][0]) + c4);
                *(((float4*)(aS + r * ASTR + In)) + c4) = v;
                idx += NTHR;
            }
        }
        __syncthreads();                   // S1: activations ready

        gemm_part<0>(aS, part, wr, kbase, kq, cp);
        __syncthreads();                   // S2: partials ready

        // reduce 4 K-quarter partials + bias; cell update
        {
            float g0 = bq0, g1 = bq1, g2 = bq2, g3 = bq3;
            #pragma unroll
            for (int k4 = 0; k4 < 4; ++k4) {
                const float* pr = part + (ur * 4 + k4) * GC + uc;
                g0 += pr[0]; g1 += pr[32]; g2 += pr[64]; g3 += pr[96];
            }
            float c2 = sigf(g1) * creg + sigf(g0) * tanhf_fast(g2);
            float h2 = sigf(g3) * tanhf_fast(c2);
            if (t >= ulen) {               // length mask: freeze state
                h2 = aS[ur * ASTR + In + rank * HCPC + uc];
                c2 = creg;
            }
            creg = c2;
            __stcg(&g_h[p ^ 1][grp][ur][rank * HCPC + uc], h2);
        }
        __syncthreads();                   // S3: all h2 stores issued

        if (tid == 0) {                    // arrive early
            __threadfence();
            unsigned old = atomicAdd(&g_arrive[grp].v, 1u);
            if ((old & 7u) == 7u)
                asm volatile("red.release.gpu.global.add.u32 [%0], %1;"
                             :: "l"(&g_phase[grp].v), "r"(1u) : "memory");
        }
        // hide x_{t+1} staging under peers' arrivals (warps 1..4)
        if (t + 1 < Tn && tid >= 32 && tid < 32 + RB * (In / 4)) {
            int q = tid - 32;
            int r = q >> 4, c4 = q & 15;
            *(((float4*)(aS + r * ASTR)) + c4) =
                *(((const float4*)(x + ((size_t)(row0 + r) * Tn + t + 1) * In)) + c4);
        }
        if (tid == 0) {
            while ((int)(ld_acq_u32(&g_phase[grp].v) - (base + nb)) < 0) { }
        }
        __syncthreads();                   // S4: release observed by whole CTA
        ++nb;
        p ^= 1;
    }

    // zero x region (decoder gates_x = bias only; kq0 still covers h cols 0..15)
    if (tid < RB * (In / 4)) {
        int r = tid >> 4, c4 = tid & 15;
        *(((float4*)(aS + r * ASTR)) + c4) = make_float4(0.f, 0.f, 0.f, 0.f);
    }

    // ================= decoder: 128 steps =================
    for (int s = 0; s < OUTL; ++s) {
        {
            int idx = tid;
            #pragma unroll
            for (int it = 0; it < 2; ++it) {
                int r = idx >> 6, c4 = idx & 63;
                float4 v = __ldcg(((const float4*)&g_h[p][grp][r][0]) + c4);
                *(((float4*)(aS + r * ASTR + In)) + c4) = v;
                idx += NTHR;
            }
        }
        __syncthreads();

        if (kq == 0) gemm_part<In / 4>(aS, part, wr, kbase, kq, cp);
        else         gemm_part<0>(aS, part, wr, kbase, kq, cp);
        __syncthreads();

        {
            float g0 = bq0, g1 = bq1, g2 = bq2, g3 = bq3;
            #pragma unroll
            for (int k4 = 0; k4 < 4; ++k4) {
                const float* pr = part + (ur * 4 + k4) * GC + uc;
                g0 += pr[0]; g1 += pr[32]; g2 += pr[64]; g3 += pr[96];
            }
            float c2 = sigf(g1) * creg + sigf(g0) * tanhf_fast(g2);
            float h2 = sigf(g3) * tanhf_fast(c2);
            creg = c2;
            __stcg(&g_h[p ^ 1][grp][ur][rank * HCPC + uc], h2);
            g_decH[row0 + ur][s][rank * HCPC + uc] = h2;   // for epilogue MLP
        }
        if (s + 1 == OUTL) break;          // no barrier needed after last step
        __syncthreads();

        if (tid == 0) {
            __threadfence();
            unsigned old = atomicAdd(&g_arrive[grp].v, 1u);
            if ((old & 7u) == 7u)
                asm volatile("red.release.gpu.global.add.u32 [%0], %1;"
                             :: "l"(&g_phase[grp].v), "r"(1u) : "memory");
            while ((int)(ld_acq_u32(&g_phase[grp].v) - (base + nb)) < 0) { }
        }
        __syncthreads();
        ++nb;
        p ^= 1;
    }
}

// ---------------- epilogue: out = relu(decH @ W1^T + b1) @ W2^T + b2 ----------------
extern "C" __global__ void __launch_bounds__(256, 1)
mlp_epilogue(const float* __restrict__ W1, const float* __restrict__ b1,
             const float* __restrict__ W2, const float* __restrict__ b2,
             float* __restrict__ out)
{
    extern __shared__ float sm[];
    float* As = sm;            // [32][256] decoder h tile
    float* Hs = sm + 32 * 256; // [32][256] relu hidden tile

    const int tid  = threadIdx.x;
    const int lane = tid & 31;
    const int w    = tid >> 5;
    const int m0   = blockIdx.x * 32;

    const float* dh = &g_decH[0][0][0];
    for (int idx = tid; idx < 32 * (Hn / 4); idx += 256) {
        int r = idx >> 6, c4 = idx & 63;
        *(((float4*)(As + r * Hn)) + c4) =
            *(((const float4*)(dh + (size_t)(m0 + r) * Hn)) + c4);
    }
    __syncthreads();

    {
        const int h = w * 32 + lane;
        float acc[32];
        const float bv = b1[h];
        #pragma unroll
        for (int r = 0; r < 32; ++r) acc[r] = bv;
        for (int k = 0; k < Hn; k += 4) {
            float4 wv = *(const float4*)(W1 + (size_t)h * Hn + k);
            #pragma unroll
            for (int r = 0; r < 32; ++r) {
                float4 av = *(const float4*)(As + r * Hn + k);
                acc[r] = fmaf(av.x, wv.x, fmaf(av.y, wv.y,
                         fmaf(av.z, wv.z, fmaf(av.w, wv.w, acc[r]))));
            }
        }
        #pragma unroll
        for (int r = 0; r < 32; ++r) Hs[r * Hn + h] = fmaxf(acc[r], 0.0f);
    }
    __syncthreads();

    {
        float o[4][2];
        const float ba = b2[lane];
        const float bb = b2[lane + 32];
        #pragma unroll
        for (int ri = 0; ri < 4; ++ri) { o[ri][0] = ba; o[ri][1] = bb; }
        for (int k = 0; k < Hn; k += 4) {
            float4 wa = *(const float4*)(W2 + (size_t)lane * Hn + k);
            float4 wb = *(const float4*)(W2 + (size_t)(lane + 32) * Hn + k);
            #pragma unroll
            for (int ri = 0; ri < 4; ++ri) {
                float4 hv = *(const float4*)(Hs + (w * 4 + ri) * Hn + k);
                o[ri][0] = fmaf(hv.x, wa.x, fmaf(hv.y, wa.y,
                           fmaf(hv.z, wa.z, fmaf(hv.w, wa.w, o[ri][0]))));
                o[ri][1] = fmaf(hv.x, wb.x, fmaf(hv.y, wb.y,
                           fmaf(hv.z, wb.z, fmaf(hv.w, wb.w, o[ri][1]))));
            }
        }
        #pragma unroll
        for (int ri = 0; ri < 4; ++ri) {
            size_t m = (size_t)(m0 + w * 4 + ri);
            out[m * Cn + lane]      = o[ri][0];
            out[m * Cn + lane + 32] = o[ri][1];
        }
    }
}

// ---------------- launch ----------------
extern "C" void kernel_launch(void* const* d_in, const int* in_sizes, int n_in,
                              void* d_out, int out_size) {
    // input order: x, lengths, [out_lengths], W_ih, W_hh, b_ih, b_hh, W1, b1, W2, b2
    const int off = (n_in >= 11) ? 3 : 2;
    const float* x       = (const float*)d_in[0];
    const int*   lengths = (const int*)  d_in[1];
    const float* W_ih    = (const float*)d_in[off + 0];
    const float* W_hh    = (const float*)d_in[off + 1];
    const float* b_ih    = (const float*)d_in[off + 2];
    const float* b_hh    = (const float*)d_in[off + 3];
    const float* W1      = (const float*)d_in[off + 4];
    const float* b1      = (const float*)d_in[off + 5];
    const float* W2      = (const float*)d_in[off + 6];
    const float* b2      = (const float*)d_in[off + 7];
    float*       out     = (float*)d_out;

    const size_t smem1 = (size_t)(RB * ASTR + RB * 4 * GC) * sizeof(float); // ~26.9 KB
    const size_t smem2 = (size_t)2 * 32 * Hn * sizeof(float);               // 64 KB

    cudaFuncSetAttribute(lstm_persistent,
                         cudaFuncAttributeMaxDynamicSharedMemorySize, (int)smem1);
    cudaFuncSetAttribute(mlp_epilogue,
                         cudaFuncAttributeMaxDynamicSharedMemorySize, (int)smem2);

    lstm_persistent<<<NCTA, NTHR, smem1>>>(x, lengths, W_ih, W_hh, b_ih, b_hh);
    mlp_epilogue<<<(Bn * OUTL) / 32, 256, smem2>>>(W1, b1, W2, b2, out);
}

// round 10
// speedup vs baseline: 5.3998x; 1.0830x over previous
#include <cuda_runtime.h>
#include <cstdint>
#include <cstddef>

// Problem constants (fixed shapes)
#define Tn    1024
#define Bn    128
#define In    64
#define Hn    256
#define Cn    64
#define OUTL  128
#define NCTA  128
#define NTHR  256
#define GRP   8              // CTAs per exchange group
#define NGRP  16             // 128/8
#define RB    8              // batch rows per group
#define GC    128            // gate-cols per CTA
#define HCPC  32             // h-cols per CTA
#define ASTR  328            // activation row stride (floats), 16B multiple
#define UXN   4              // x units (4 k each) per quarter  -> 16 k
#define UHN   16             // h units (4 k each) per quarter  -> 64 k

typedef unsigned long long ull;

// ---------------- persistent device state ----------------
__device__ float g_h[2][NGRP][RB][Hn];       // double-buffered hidden state (version v -> buf v&1)
__device__ float g_decH[Bn][OUTL][Hn];       // decoder hidden states for epilogue

struct alignas(32) Flag { unsigned v; unsigned pad[7]; };
__device__ Flag g_flag[NGRP][GRP];           // per-producer published version (monotonic)

// ---------------- helpers ----------------
__device__ __forceinline__ unsigned ld_acq_u32(const unsigned* p) {
    unsigned v;
    asm volatile("ld.acquire.gpu.global.u32 %0, [%1];" : "=r"(v) : "l"(p) : "memory");
    return v;
}
__device__ __forceinline__ void st_rel_u32(unsigned* p, unsigned v) {
    asm volatile("st.release.gpu.global.u32 [%0], %1;" :: "l"(p), "r"(v) : "memory");
}
__device__ __forceinline__ ull pk2(float x, float y) {
    ull r; asm("mov.b64 %0, {%1, %2};" : "=l"(r) : "f"(x), "f"(y)); return r;
}
__device__ __forceinline__ void upk2(ull v, float& x, float& y) {
    asm("mov.b64 {%0, %1}, %2;" : "=f"(x), "=f"(y) : "l"(v));
}
__device__ __forceinline__ ull ffma2(ull a, ull b, ull c) {
    ull d; asm("fma.rn.f32x2 %0, %1, %2, %3;" : "=l"(d) : "l"(a), "l"(b), "l"(c));
    return d;
}
__device__ __forceinline__ float sigf(float x) {
    return 1.0f / (1.0f + __expf(-x));
}
__device__ __forceinline__ float tanhf_fast(float x) {
    x = fminf(fmaxf(x, -15.0f), 15.0f);
    float e = __expf(2.0f * x);
    return (e - 1.0f) / (e + 1.0f);
}

// GEMM over this thread's K-slice: x[16kq,16kq+16) (if WITHX) + h[64kq,64kq+64).
// Weights register-resident: wr[0..15] = x units, wr[16..79] = h units.
// Activations via broadcast LDS.128 (same address across warp).
template<bool WITHX>
__device__ __forceinline__ void gemm_qtr(const float* __restrict__ aS,
                                         float* __restrict__ part,
                                         const ull* __restrict__ wr,
                                         int kq, int cp)
{
    const int xoff = 16 * kq;
    const int hoff = In + 64 * kq;
    #pragma unroll 1
    for (int r0 = 0; r0 < RB; r0 += 2) {
        const float* b0 = aS + r0 * ASTR;
        const float* b1 = b0 + ASTR;
        ull a00 = 0ull, a01 = 0ull, a10 = 0ull, a11 = 0ull;
        if (WITHX) {
            #pragma unroll
            for (int u = 0; u < UXN; ++u) {
                ulonglong2 A0 = *(const ulonglong2*)(b0 + xoff + 4 * u);
                a00 = ffma2(A0.x, wr[4 * u + 0], a00);
                a00 = ffma2(A0.y, wr[4 * u + 1], a00);
                a01 = ffma2(A0.x, wr[4 * u + 2], a01);
                a01 = ffma2(A0.y, wr[4 * u + 3], a01);
                ulonglong2 A1 = *(const ulonglong2*)(b1 + xoff + 4 * u);
                a10 = ffma2(A1.x, wr[4 * u + 0], a10);
                a10 = ffma2(A1.y, wr[4 * u + 1], a10);
                a11 = ffma2(A1.x, wr[4 * u + 2], a11);
                a11 = ffma2(A1.y, wr[4 * u + 3], a11);
            }
        }
        #pragma unroll
        for (int u = 0; u < UHN; ++u) {
            const ull* wp = wr + 16 + 4 * u;
            ulonglong2 A0 = *(const ulonglong2*)(b0 + hoff + 4 * u);
            a00 = ffma2(A0.x, wp[0], a00);
            a00 = ffma2(A0.y, wp[1], a00);
            a01 = ffma2(A0.x, wp[2], a01);
            a01 = ffma2(A0.y, wp[3], a01);
            ulonglong2 A1 = *(const ulonglong2*)(b1 + hoff + 4 * u);
            a10 = ffma2(A1.x, wp[0], a10);
            a10 = ffma2(A1.y, wp[1], a10);
            a11 = ffma2(A1.x, wp[2], a11);
            a11 = ffma2(A1.y, wp[3], a11);
        }
        float lo, hi, s00, s01, s10, s11;
        upk2(a00, lo, hi); s00 = lo + hi;
        upk2(a01, lo, hi); s01 = lo + hi;
        upk2(a10, lo, hi); s10 = lo + hi;
        upk2(a11, lo, hi); s11 = lo + hi;
        *(float2*)(part + ((r0 + 0) * 4 + kq) * GC + 2 * cp) = make_float2(s00, s01);
        *(float2*)(part + ((r0 + 1) * 4 + kq) * GC + 2 * cp) = make_float2(s10, s11);
    }
}

// ---------------- persistent encoder + decoder kernel ----------------
extern "C" __global__ void __launch_bounds__(NTHR, 1)
lstm_persistent(const float* __restrict__ x, const int* __restrict__ lengths,
                const float* __restrict__ W_ih, const float* __restrict__ W_hh,
                const float* __restrict__ b_ih, const float* __restrict__ b_hh)
{
    extern __shared__ float sm[];
    float* aS   = sm;                  // [RB][ASTR] activations [x_t | h_t]
    float* part = sm + RB * ASTR;      // [RB][4][GC] K-quarter partials
    unsigned* sbase = (unsigned*)(part + RB * 4 * GC);

    const int tid  = threadIdx.x;
    const int lane = tid & 31;
    const int wid  = tid >> 5;         // warp 0..7 == producer rank this warp stages
    const int grp  = blockIdx.x >> 3;  // group 0..15
    const int rank = blockIdx.x & 7;   // rank in group 0..7
    const int row0 = grp * RB;

    // GEMM role: col-pair + K-quarter
    const int cp = tid & 63;           // col pair 0..63
    const int kq = tid >> 6;           // K quarter 0..3
    const int c0 = cp * 2, c1 = cp * 2 + 1;

    // ---- weights into registers (once): 2 cols x (16 x-k + 64 h-k) = 80 b64 ----
    ull wr[80];
    {
        const int grow0 = (c0 >> 5) * Hn + rank * HCPC + (c0 & 31);
        const int grow1 = (c1 >> 5) * Hn + rank * HCPC + (c1 & 31);
        #pragma unroll
        for (int u = 0; u < UXN; ++u) {         // x part: k = 16*kq + 4u + j
            float w0[4], w1[4];
            #pragma unroll
            for (int j = 0; j < 4; ++j) {
                int kk = 16 * kq + 4 * u + j;
                w0[j] = W_ih[(size_t)grow0 * In + kk];
                w1[j] = W_ih[(size_t)grow1 * In + kk];
            }
            wr[4 * u + 0] = pk2(w0[0], w0[1]);
            wr[4 * u + 1] = pk2(w0[2], w0[3]);
            wr[4 * u + 2] = pk2(w1[0], w1[1]);
            wr[4 * u + 3] = pk2(w1[2], w1[3]);
        }
        #pragma unroll
        for (int u = 0; u < UHN; ++u) {         // h part: k = 64*kq + 4u + j
            float w0[4], w1[4];
            #pragma unroll
            for (int j = 0; j < 4; ++j) {
                int kk = 64 * kq + 4 * u + j;
                w0[j] = W_hh[(size_t)grow0 * Hn + kk];
                w1[j] = W_hh[(size_t)grow1 * Hn + kk];
            }
            wr[16 + 4 * u + 0] = pk2(w0[0], w0[1]);
            wr[16 + 4 * u + 1] = pk2(w0[2], w0[3]);
            wr[16 + 4 * u + 2] = pk2(w1[0], w1[1]);
            wr[16 + 4 * u + 3] = pk2(w1[2], w1[3]);
        }
    }

    // update role: thread owns (row ur, local h-col uc)
    const int ur = tid >> 5, uc = tid & 31;
    float bq0, bq1, bq2, bq3;
    {
        int c = rank * HCPC + uc;
        bq0 = b_ih[0 * Hn + c] + b_hh[0 * Hn + c];
        bq1 = b_ih[1 * Hn + c] + b_hh[1 * Hn + c];
        bq2 = b_ih[2 * Hn + c] + b_hh[2 * Hn + c];
        bq3 = b_ih[3 * Hn + c] + b_hh[3 * Hn + c];
    }
    const int ulen = lengths[row0 + ur];
    float creg = 0.0f;

    // ---- init: snapshot own flag (uniform across ranks), zero own h0 slab, stage x_0 ----
    if (tid == 0) *sbase = ld_acq_u32(&g_flag[grp][rank].v);
    if (tid < 64) {                              // own slab of buffer 0: 8 rows x 8 float4
        int r = tid >> 3, c4 = tid & 7;
        *(((float4*)&g_h[0][grp][r][rank * HCPC]) + c4) = make_float4(0.f, 0.f, 0.f, 0.f);
    }
    if (tid < RB * (In / 4)) {                   // x_0: 8 rows x 16 float4
        int r = tid >> 4, c4 = tid & 15;
        *(((float4*)(aS + r * ASTR)) + c4) =
            *(((const float4*)(x + ((size_t)(row0 + r) * Tn) * In)) + c4);
    }
    __syncthreads();
    const unsigned base = *sbase;
    if (tid == 0) st_rel_u32(&g_flag[grp][rank].v, base + 1);   // version 0 (zeros) published

    // ================= encoder: 1024 steps =================
    for (int t = 0; t < Tn; ++t) {
        const unsigned tgt = base + 1 + (unsigned)t;            // need version t
        // poll only this quarter's two producer ranks (lanes 0,1)
        if (lane < 2) {
            const unsigned* fp = &g_flag[grp][2 * kq + lane].v;
            while ((int)(ld_acq_u32(fp) - tgt) < 0) { }
        }
        __syncwarp();
        // warp 'wid' stages rank 'wid' slab (8 rows x 32 cols) from buffer t&1
        {
            const float* src = &g_h[t & 1][grp][0][wid * HCPC];
            float*       dst = aS + In + wid * HCPC;
            #pragma unroll
            for (int j = 0; j < 2; ++j) {
                int idx = lane + 32 * j, r = idx >> 3, c4 = idx & 7;
                float4 v = __ldcg(((const float4*)(src + (size_t)r * Hn)) + c4);
                *(((float4*)(dst + r * ASTR)) + c4) = v;
            }
        }
        asm volatile("bar.sync %0, 64;" :: "r"(kq + 1) : "memory");  // pair-warp sync

        // prefetch x_{t+1} into registers (DRAM latency hidden under GEMM)
        float4 xv;
        const bool hasx = (t + 1 < Tn) && (tid < RB * (In / 4));
        if (hasx) {
            int r = tid >> 4, c4 = tid & 15;
            xv = *(((const float4*)(x + ((size_t)(row0 + r) * Tn + t + 1) * In)) + c4);
        }

        gemm_qtr<true>(aS, part, wr, kq, cp);
        __syncthreads();                                         // S2: partials ready

        // reduce 4 K-quarter partials + bias; cell update for (ur, uc)
        {
            float g0 = bq0, g1 = bq1, g2 = bq2, g3 = bq3;
            #pragma unroll
            for (int k4 = 0; k4 < 4; ++k4) {
                const float* pr = part + (ur * 4 + k4) * GC + uc;
                g0 += pr[0]; g1 += pr[32]; g2 += pr[64]; g3 += pr[96];
            }
            float c2 = sigf(g1) * creg + sigf(g0) * tanhf_fast(g2);
            float h2 = sigf(g3) * tanhf_fast(c2);
            if (t >= ulen) {                                     // freeze masked rows
                h2 = aS[ur * ASTR + In + rank * HCPC + uc];
                c2 = creg;
            }
            creg = c2;
            __stcg(&g_h[(t + 1) & 1][grp][ur][rank * HCPC + uc], h2);
        }
        if (hasx) {                                              // store x_{t+1} (WAR safe: after S2)
            int r = tid >> 4, c4 = tid & 15;
            *(((float4*)(aS + r * ASTR)) + c4) = xv;
        }
        __syncthreads();                                         // S3: h2 stores + x staged
        if (tid == 0) st_rel_u32(&g_flag[grp][rank].v, tgt + 1); // publish version t+1
    }

    // ================= decoder: 128 steps (gates_x = bias) =================
    for (int s = 0; s < OUTL; ++s) {
        const int u = Tn + s;
        const unsigned tgt = base + 1 + (unsigned)u;
        if (lane < 2) {
            const unsigned* fp = &g_flag[grp][2 * kq + lane].v;
            while ((int)(ld_acq_u32(fp) - tgt) < 0) { }
        }
        __syncwarp();
        {
            const float* src = &g_h[u & 1][grp][0][wid * HCPC];
            float*       dst = aS + In + wid * HCPC;
            #pragma unroll
            for (int j = 0; j < 2; ++j) {
                int idx = lane + 32 * j, r = idx >> 3, c4 = idx & 7;
                float4 v = __ldcg(((const float4*)(src + (size_t)r * Hn)) + c4);
                *(((float4*)(dst + r * ASTR)) + c4) = v;
            }
        }
        asm volatile("bar.sync %0, 64;" :: "r"(kq + 1) : "memory");

        gemm_qtr<false>(aS, part, wr, kq, cp);
        __syncthreads();

        {
            float g0 = bq0, g1 = bq1, g2 = bq2, g3 = bq3;
            #pragma unroll
            for (int k4 = 0; k4 < 4; ++k4) {
                const float* pr = part + (ur * 4 + k4) * GC + uc;
                g0 += pr[0]; g1 += pr[32]; g2 += pr[64]; g3 += pr[96];
            }
            float c2 = sigf(g1) * creg + sigf(g0) * tanhf_fast(g2);
            float h2 = sigf(g3) * tanhf_fast(c2);
            creg = c2;
            __stcg(&g_h[(u + 1) & 1][grp][ur][rank * HCPC + uc], h2);
            g_decH[row0 + ur][s][rank * HCPC + uc] = h2;         // for epilogue MLP
        }
        if (s + 1 == OUTL) break;                                // last step: no publish
        __syncthreads();
        if (tid == 0) st_rel_u32(&g_flag[grp][rank].v, tgt + 1);
    }
}

// ---------------- epilogue: out = relu(decH @ W1^T + b1) @ W2^T + b2 ----------------
extern "C" __global__ void __launch_bounds__(256, 1)
mlp_epilogue(const float* __restrict__ W1, const float* __restrict__ b1,
             const float* __restrict__ W2, const float* __restrict__ b2,
             float* __restrict__ out)
{
    extern __shared__ float sm[];
    float* As = sm;            // [32][256] decoder h tile
    float* Hs = sm + 32 * 256; // [32][256] relu hidden tile

    const int tid  = threadIdx.x;
    const int lane = tid & 31;
    const int w    = tid >> 5;
    const int m0   = blockIdx.x * 32;

    const float* dh = &g_decH[0][0][0];
    for (int idx = tid; idx < 32 * (Hn / 4); idx += 256) {
        int r = idx >> 6, c4 = idx & 63;
        *(((float4*)(As + r * Hn)) + c4) =
            *(((const float4*)(dh + (size_t)(m0 + r) * Hn)) + c4);
    }
    __syncthreads();

    {
        const int h = w * 32 + lane;
        float acc[32];
        const float bv = b1[h];
        #pragma unroll
        for (int r = 0; r < 32; ++r) acc[r] = bv;
        for (int k = 0; k < Hn; k += 4) {
            float4 wv = *(const float4*)(W1 + (size_t)h * Hn + k);
            #pragma unroll
            for (int r = 0; r < 32; ++r) {
                float4 av = *(const float4*)(As + r * Hn + k);
                acc[r] = fmaf(av.x, wv.x, fmaf(av.y, wv.y,
                         fmaf(av.z, wv.z, fmaf(av.w, wv.w, acc[r]))));
            }
        }
        #pragma unroll
        for (int r = 0; r < 32; ++r) Hs[r * Hn + h] = fmaxf(acc[r], 0.0f);
    }
    __syncthreads();

    {
        float o[4][2];
        const float ba = b2[lane];
        const float bb = b2[lane + 32];
        #pragma unroll
        for (int ri = 0; ri < 4; ++ri) { o[ri][0] = ba; o[ri][1] = bb; }
        for (int k = 0; k < Hn; k += 4) {
            float4 wa = *(const float4*)(W2 + (size_t)lane * Hn + k);
            float4 wb = *(const float4*)(W2 + (size_t)(lane + 32) * Hn + k);
            #pragma unroll
            for (int ri = 0; ri < 4; ++ri) {
                float4 hv = *(const float4*)(Hs + (w * 4 + ri) * Hn + k);
                o[ri][0] = fmaf(hv.x, wa.x, fmaf(hv.y, wa.y,
                           fmaf(hv.z, wa.z, fmaf(hv.w, wa.w, o[ri][0]))));
                o[ri][1] = fmaf(hv.x, wb.x, fmaf(hv.y, wb.y,
                           fmaf(hv.z, wb.z, fmaf(hv.w, wb.w, o[ri][1]))));
            }
        }
        #pragma unroll
        for (int ri = 0; ri < 4; ++ri) {
            size_t m = (size_t)(m0 + w * 4 + ri);
            out[m * Cn + lane]      = o[ri][0];
            out[m * Cn + lane + 32] = o[ri][1];
        }
    }
}

// ---------------- launch ----------------
extern "C" void kernel_launch(void* const* d_in, const int* in_sizes, int n_in,
                              void* d_out, int out_size) {
    // input order: x, lengths, [out_lengths], W_ih, W_hh, b_ih, b_hh, W1, b1, W2, b2
    const int off = (n_in >= 11) ? 3 : 2;
    const float* x       = (const float*)d_in[0];
    const int*   lengths = (const int*)  d_in[1];
    const float* W_ih    = (const float*)d_in[off + 0];
    const float* W_hh    = (const float*)d_in[off + 1];
    const float* b_ih    = (const float*)d_in[off + 2];
    const float* b_hh    = (const float*)d_in[off + 3];
    const float* W1      = (const float*)d_in[off + 4];
    const float* b1      = (const float*)d_in[off + 5];
    const float* W2      = (const float*)d_in[off + 6];
    const float* b2      = (const float*)d_in[off + 7];
    float*       out     = (float*)d_out;

    const size_t smem1 = (size_t)(RB * ASTR + RB * 4 * GC) * sizeof(float) + 16; // ~26.9 KB
    const size_t smem2 = (size_t)2 * 32 * Hn * sizeof(float);                    // 64 KB

    cudaFuncSetAttribute(lstm_persistent,
                         cudaFuncAttributeMaxDynamicSharedMemorySize, (int)smem1);
    cudaFuncSetAttribute(mlp_epilogue,
                         cudaFuncAttributeMaxDynamicSharedMemorySize, (int)smem2);

    lstm_persistent<<<NCTA, NTHR, smem1>>>(x, lengths, W_ih, W_hh, b_ih, b_hh);
    mlp_epilogue<<<(Bn * OUTL) / 32, 256, smem2>>>(W1, b1, W2, b2, out);
}

// round 11
// speedup vs baseline: 5.6508x; 1.0465x over previous
#include <cuda_runtime.h>
#include <cstdint>
#include <cstddef>

// Problem constants (fixed shapes)
#define Tn    1024
#define Bn    128
#define In    64
#define Hn    256
#define Cn    64
#define OUTL  128
#define NCTA  128
#define NTHR  256
#define GRP   8              // CTAs per exchange group
#define NGRP  16             // 128/8
#define RB    8              // batch rows per group
#define GC    128            // gate-cols per CTA
#define HCPC  32             // h-cols per CTA
#define ASTR  328            // activation row stride (floats), 16B multiple
#define ABUF  (RB * ASTR)    // one activation buffer (floats)
#define PBUF  (RB * 4 * GC)  // one partials buffer (floats)

typedef unsigned long long ull;

// ---------------- persistent device state ----------------
__device__ float g_h[2][NGRP][RB][Hn];       // double-buffered hidden state (h_t -> buf t&1)
__device__ float g_decH[Bn][OUTL][Hn];       // decoder hidden states for epilogue

struct alignas(32) Flag { unsigned v; unsigned pad[7]; };
__device__ Flag g_flag[NGRP][GRP];           // per-producer counter: +1 per warp per step

// ---------------- helpers ----------------
__device__ __forceinline__ unsigned ld_acq_u32(const unsigned* p) {
    unsigned v;
    asm volatile("ld.acquire.gpu.global.u32 %0, [%1];" : "=r"(v) : "l"(p) : "memory");
    return v;
}
__device__ __forceinline__ void rel_add1(unsigned* p) {
    asm volatile("red.release.gpu.global.add.u32 [%0], %1;" :: "l"(p), "r"(1u) : "memory");
}
__device__ __forceinline__ ull pk2(float x, float y) {
    ull r; asm("mov.b64 %0, {%1, %2};" : "=l"(r) : "f"(x), "f"(y)); return r;
}
__device__ __forceinline__ void upk2(ull v, float& x, float& y) {
    asm("mov.b64 {%0, %1}, %2;" : "=f"(x), "=f"(y) : "l"(v));
}
__device__ __forceinline__ ull ffma2(ull a, ull b, ull c) {
    ull d; asm("fma.rn.f32x2 %0, %1, %2, %3;" : "=l"(d) : "l"(a), "l"(b), "l"(c));
    return d;
}
__device__ __forceinline__ float sigf(float x) {
    return 1.0f / (1.0f + __expf(-x));
}
__device__ __forceinline__ float tanhf_fast(float x) {
    x = fminf(fmaxf(x, -15.0f), 15.0f);
    float e = __expf(2.0f * x);
    return (e - 1.0f) / (e + 1.0f);
}

// x-phase: partials over x[16kq,16kq+16) into sx[16] register array.
__device__ __forceinline__ void gemm_x(const float* __restrict__ aS,
                                       float* __restrict__ sx,
                                       const ull* __restrict__ wr, int kq)
{
    const int xoff = 16 * kq;
    #pragma unroll
    for (int rp = 0; rp < 4; ++rp) {
        const float* b0 = aS + (2 * rp) * ASTR + xoff;
        const float* b1 = b0 + ASTR;
        ull a00 = 0ull, a01 = 0ull, a10 = 0ull, a11 = 0ull;
        #pragma unroll
        for (int u = 0; u < 4; ++u) {
            ulonglong2 A0 = *(const ulonglong2*)(b0 + 4 * u);
            a00 = ffma2(A0.x, wr[4 * u + 0], a00);
            a00 = ffma2(A0.y, wr[4 * u + 1], a00);
            a01 = ffma2(A0.x, wr[4 * u + 2], a01);
            a01 = ffma2(A0.y, wr[4 * u + 3], a01);
            ulonglong2 A1 = *(const ulonglong2*)(b1 + 4 * u);
            a10 = ffma2(A1.x, wr[4 * u + 0], a10);
            a10 = ffma2(A1.y, wr[4 * u + 1], a10);
            a11 = ffma2(A1.x, wr[4 * u + 2], a11);
            a11 = ffma2(A1.y, wr[4 * u + 3], a11);
        }
        float lo, hi;
        upk2(a00, lo, hi); sx[4 * rp + 0] = lo + hi;
        upk2(a01, lo, hi); sx[4 * rp + 1] = lo + hi;
        upk2(a10, lo, hi); sx[4 * rp + 2] = lo + hi;
        upk2(a11, lo, hi); sx[4 * rp + 3] = lo + hi;
    }
}

// h-phase: accumulate h[64kq,64kq+64), optionally seeded with x partials; store to part.
template<bool WITHSX>
__device__ __forceinline__ void gemm_h(const float* __restrict__ aS,
                                       float* __restrict__ part,
                                       const float* __restrict__ sx,
                                       const ull* __restrict__ wr,
                                       int kq, int cp)
{
    const int hoff = In + 64 * kq;
    #pragma unroll
    for (int rp = 0; rp < 4; ++rp) {
        const float* b0 = aS + (2 * rp) * ASTR + hoff;
        const float* b1 = b0 + ASTR;
        ull a00, a01, a10, a11;
        if (WITHSX) {
            a00 = pk2(sx[4 * rp + 0], 0.f);
            a01 = pk2(sx[4 * rp + 1], 0.f);
            a10 = pk2(sx[4 * rp + 2], 0.f);
            a11 = pk2(sx[4 * rp + 3], 0.f);
        } else {
            a00 = a01 = a10 = a11 = 0ull;
        }
        #pragma unroll
        for (int u = 0; u < 16; ++u) {
            const ull* wp = wr + 16 + 4 * u;
            ulonglong2 A0 = *(const ulonglong2*)(b0 + 4 * u);
            a00 = ffma2(A0.x, wp[0], a00);
            a00 = ffma2(A0.y, wp[1], a00);
            a01 = ffma2(A0.x, wp[2], a01);
            a01 = ffma2(A0.y, wp[3], a01);
            ulonglong2 A1 = *(const ulonglong2*)(b1 + 4 * u);
            a10 = ffma2(A1.x, wp[0], a10);
            a10 = ffma2(A1.y, wp[1], a10);
            a11 = ffma2(A1.x, wp[2], a11);
            a11 = ffma2(A1.y, wp[3], a11);
        }
        float lo, hi, s00, s01, s10, s11;
        upk2(a00, lo, hi); s00 = lo + hi;
        upk2(a01, lo, hi); s01 = lo + hi;
        upk2(a10, lo, hi); s10 = lo + hi;
        upk2(a11, lo, hi); s11 = lo + hi;
        *(float2*)(part + ((2 * rp + 0) * 4 + kq) * GC + 2 * cp) = make_float2(s00, s01);
        *(float2*)(part + ((2 * rp + 1) * 4 + kq) * GC + 2 * cp) = make_float2(s10, s11);
    }
}

// ---------------- persistent encoder + decoder kernel ----------------
extern "C" __global__ void __launch_bounds__(NTHR, 1)
lstm_persistent(const float* __restrict__ x, const int* __restrict__ lengths,
                const float* __restrict__ W_ih, const float* __restrict__ W_hh,
                const float* __restrict__ b_ih, const float* __restrict__ b_hh)
{
    extern __shared__ float sm[];
    float* smA = sm;                       // [2][RB][ASTR] activations [x_t | h_t]
    float* smP = sm + 2 * ABUF;            // [2][RB][4][GC] K-quarter partials
    unsigned* sbase = (unsigned*)(smP + 2 * PBUF);

    const int tid  = threadIdx.x;
    const int lane = tid & 31;
    const int wid  = tid >> 5;             // warp 0..7: stages slab 'wid', updates row 'wid'
    const int grp  = blockIdx.x >> 3;      // group 0..15
    const int rank = blockIdx.x & 7;       // rank in group 0..7
    const int row0 = grp * RB;

    // GEMM role: col-pair + K-quarter (pair of warps {2kq, 2kq+1})
    const int cp = tid & 63;
    const int kq = tid >> 6;
    const int c0 = cp * 2, c1 = cp * 2 + 1;

    // ---- weights into registers (once): wr[0..15]=x-units, wr[16..79]=h-units ----
    ull wr[80];
    {
        const int grow0 = (c0 >> 5) * Hn + rank * HCPC + (c0 & 31);
        const int grow1 = (c1 >> 5) * Hn + rank * HCPC + (c1 & 31);
        #pragma unroll
        for (int u = 0; u < 4; ++u) {
            float w0[4], w1[4];
            #pragma unroll
            for (int j = 0; j < 4; ++j) {
                int kk = 16 * kq + 4 * u + j;
                w0[j] = W_ih[(size_t)grow0 * In + kk];
                w1[j] = W_ih[(size_t)grow1 * In + kk];
            }
            wr[4 * u + 0] = pk2(w0[0], w0[1]);
            wr[4 * u + 1] = pk2(w0[2], w0[3]);
            wr[4 * u + 2] = pk2(w1[0], w1[1]);
            wr[4 * u + 3] = pk2(w1[2], w1[3]);
        }
        #pragma unroll
        for (int u = 0; u < 16; ++u) {
            float w0[4], w1[4];
            #pragma unroll
            for (int j = 0; j < 4; ++j) {
                int kk = 64 * kq + 4 * u + j;
                w0[j] = W_hh[(size_t)grow0 * Hn + kk];
                w1[j] = W_hh[(size_t)grow1 * Hn + kk];
            }
            wr[16 + 4 * u + 0] = pk2(w0[0], w0[1]);
            wr[16 + 4 * u + 1] = pk2(w0[2], w0[3]);
            wr[16 + 4 * u + 2] = pk2(w1[0], w1[1]);
            wr[16 + 4 * u + 3] = pk2(w1[2], w1[3]);
        }
    }

    // update role: warp wid owns row wid, lane owns local h-col
    float bq0, bq1, bq2, bq3;
    {
        int c = rank * HCPC + lane;
        bq0 = b_ih[0 * Hn + c] + b_hh[0 * Hn + c];
        bq1 = b_ih[1 * Hn + c] + b_hh[1 * Hn + c];
        bq2 = b_ih[2 * Hn + c] + b_hh[2 * Hn + c];
        bq3 = b_ih[3 * Hn + c] + b_hh[3 * Hn + c];
    }
    const int ulen = lengths[row0 + wid];
    float creg = 0.0f;

    // ---- init: snapshot base, zero own h0 slab row, stage x_0 into buffer 0 ----
    if (tid == 0) *sbase = ld_acq_u32(&g_flag[grp][rank].v);
    if (lane < 8)                                   // warp wid zeroes row wid of own slab
        *(((float4*)&g_h[0][grp][wid][rank * HCPC]) + lane) = make_float4(0.f, 0.f, 0.f, 0.f);
    if ((wid & 1) == 0) {                           // even warp of pair kq stages its x slice
        int r = lane >> 2, c4 = lane & 3;
        float4 v = *(((const float4*)(x + ((size_t)(row0 + r) * Tn) * In)) + 4 * kq + c4);
        *(((float4*)(smA + r * ASTR)) + 4 * kq + c4) = v;
    }
    __syncthreads();
    const unsigned base = *sbase;
    if (lane == 0) rel_add1(&g_flag[grp][rank].v);  // 8 warps -> +8: h_0 published

    // ================= encoder: 1024 steps =================
    for (int t = 0; t < Tn; ++t) {
        float* aCur = smA + (t & 1) * ABUF;
        float* aNxt = smA + ((t + 1) & 1) * ABUF;
        float* pCur = smP + (t & 1) * PBUF;

        // (a) x-phase (no h dependency; hides peers' publish latency)
        float sx[16];
        gemm_x(aCur, sx, wr, kq);

        // (b) poll ONLY own slab's producer, stage slab 'wid' into aCur
        if (lane == 0) {
            const unsigned* fp = &g_flag[grp][wid].v;
            const unsigned tgt = base + 8u * (unsigned)(t + 1);
            while ((int)(ld_acq_u32(fp) - tgt) < 0) { }
        }
        __syncwarp();
        {
            const float* src = &g_h[t & 1][grp][0][wid * HCPC];
            float*       dst = aCur + In + wid * HCPC;
            #pragma unroll
            for (int j = 0; j < 2; ++j) {
                int idx = lane + 32 * j, r = idx >> 3, c4 = idx & 7;
                float4 v = __ldcg(((const float4*)(src + (size_t)r * Hn)) + c4);
                *(((float4*)(dst + r * ASTR)) + c4) = v;
            }
        }
        asm volatile("bar.sync %0, 64;" :: "r"(kq + 1) : "memory");  // pair: both slabs staged

        // x_{t+1} prefetch to regs (DRAM latency hidden under h-phase)
        float4 xv;
        const bool dox = ((wid & 1) == 0) && (t + 1 < Tn);
        if (dox) {
            int r = lane >> 2, c4 = lane & 3;
            xv = *(((const float4*)(x + ((size_t)(row0 + r) * Tn + t + 1) * In)) + 4 * kq + c4);
        }

        // (c) h-phase, seeded by x partials
        gemm_h<true>(aCur, pCur, sx, wr, kq, cp);
        if (dox) {
            int r = lane >> 2, c4 = lane & 3;
            *(((float4*)(aNxt + r * ASTR)) + 4 * kq + c4) = xv;
        }
        __syncthreads();                                             // the ONE CTA sync

        // (e) reduce + cell update for (row wid, hcol lane)
        {
            float g0 = bq0, g1 = bq1, g2 = bq2, g3 = bq3;
            #pragma unroll
            for (int k4 = 0; k4 < 4; ++k4) {
                const float* pr = pCur + (wid * 4 + k4) * GC + lane;
                g0 += pr[0]; g1 += pr[32]; g2 += pr[64]; g3 += pr[96];
            }
            float c2 = sigf(g1) * creg + sigf(g0) * tanhf_fast(g2);
            float h2 = sigf(g3) * tanhf_fast(c2);
            if (t >= ulen) {                                         // freeze masked rows
                h2 = aCur[wid * ASTR + In + rank * HCPC + lane];
                c2 = creg;
            }
            creg = c2;
            __stcg(&g_h[(t + 1) & 1][grp][wid][rank * HCPC + lane], h2);
        }
        __syncwarp();
        if (lane == 0) rel_add1(&g_flag[grp][rank].v);               // per-warp publish
    }

    // ================= decoder: 128 steps (gates_x = bias) =================
    for (int s = 0; s < OUTL; ++s) {
        const int u = Tn + s;
        float* aCur = smA + (u & 1) * ABUF;
        float* pCur = smP + (u & 1) * PBUF;

        if (lane == 0) {
            const unsigned* fp = &g_flag[grp][wid].v;
            const unsigned tgt = base + 8u * (unsigned)(u + 1);
            while ((int)(ld_acq_u32(fp) - tgt) < 0) { }
        }
        __syncwarp();
        {
            const float* src = &g_h[u & 1][grp][0][wid * HCPC];
            float*       dst = aCur + In + wid * HCPC;
            #pragma unroll
            for (int j = 0; j < 2; ++j) {
                int idx = lane + 32 * j, r = idx >> 3, c4 = idx & 7;
                float4 v = __ldcg(((const float4*)(src + (size_t)r * Hn)) + c4);
                *(((float4*)(dst + r * ASTR)) + c4) = v;
            }
        }
        asm volatile("bar.sync %0, 64;" :: "r"(kq + 1) : "memory");

        gemm_h<false>(aCur, pCur, (const float*)nullptr, wr, kq, cp);
        __syncthreads();

        {
            float g0 = bq0, g1 = bq1, g2 = bq2, g3 = bq3;
            #pragma unroll
            for (int k4 = 0; k4 < 4; ++k4) {
                const float* pr = pCur + (wid * 4 + k4) * GC + lane;
                g0 += pr[0]; g1 += pr[32]; g2 += pr[64]; g3 += pr[96];
            }
            float c2 = sigf(g1) * creg + sigf(g0) * tanhf_fast(g2);
            float h2 = sigf(g3) * tanhf_fast(c2);
            creg = c2;
            __stcg(&g_h[(u + 1) & 1][grp][wid][rank * HCPC + lane], h2);
            g_decH[row0 + wid][s][rank * HCPC + lane] = h2;          // for epilogue MLP
        }
        if (s + 1 < OUTL) {
            __syncwarp();
            if (lane == 0) rel_add1(&g_flag[grp][rank].v);
        }
    }
}

// ---------------- epilogue: out = relu(decH @ W1^T + b1) @ W2^T + b2 ----------------
extern "C" __global__ void __launch_bounds__(256, 1)
mlp_epilogue(const float* __restrict__ W1, const float* __restrict__ b1,
             const float* __restrict__ W2, const float* __restrict__ b2,
             float* __restrict__ out)
{
    extern __shared__ float sm[];
    float* As = sm;            // [32][256] decoder h tile
    float* Hs = sm + 32 * 256; // [32][256] relu hidden tile

    const int tid  = threadIdx.x;
    const int lane = tid & 31;
    const int w    = tid >> 5;
    const int m0   = blockIdx.x * 32;

    const float* dh = &g_decH[0][0][0];
    for (int idx = tid; idx < 32 * (Hn / 4); idx += 256) {
        int r = idx >> 6, c4 = idx & 63;
        *(((float4*)(As + r * Hn)) + c4) =
            *(((const float4*)(dh + (size_t)(m0 + r) * Hn)) + c4);
    }
    __syncthreads();

    {
        const int h = w * 32 + lane;
        float acc[32];
        const float bv = b1[h];
        #pragma unroll
        for (int r = 0; r < 32; ++r) acc[r] = bv;
        for (int k = 0; k < Hn; k += 4) {
            float4 wv = *(const float4*)(W1 + (size_t)h * Hn + k);
            #pragma unroll
            for (int r = 0; r < 32; ++r) {
                float4 av = *(const float4*)(As + r * Hn + k);
                acc[r] = fmaf(av.x, wv.x, fmaf(av.y, wv.y,
                         fmaf(av.z, wv.z, fmaf(av.w, wv.w, acc[r]))));
            }
        }
        #pragma unroll
        for (int r = 0; r < 32; ++r) Hs[r * Hn + h] = fmaxf(acc[r], 0.0f);
    }
    __syncthreads();

    {
        float o[4][2];
        const float ba = b2[lane];
        const float bb = b2[lane + 32];
        #pragma unroll
        for (int ri = 0; ri < 4; ++ri) { o[ri][0] = ba; o[ri][1] = bb; }
        for (int k = 0; k < Hn; k += 4) {
            float4 wa = *(const float4*)(W2 + (size_t)lane * Hn + k);
            float4 wb = *(const float4*)(W2 + (size_t)(lane + 32) * Hn + k);
            #pragma unroll
            for (int ri = 0; ri < 4; ++ri) {
                float4 hv = *(const float4*)(Hs + (w * 4 + ri) * Hn + k);
                o[ri][0] = fmaf(hv.x, wa.x, fmaf(hv.y, wa.y,
                           fmaf(hv.z, wa.z, fmaf(hv.w, wa.w, o[ri][0]))));
                o[ri][1] = fmaf(hv.x, wb.x, fmaf(hv.y, wb.y,
                           fmaf(hv.z, wb.z, fmaf(hv.w, wb.w, o[ri][1]))));
            }
        }
        #pragma unroll
        for (int ri = 0; ri < 4; ++ri) {
            size_t m = (size_t)(m0 + w * 4 + ri);
            out[m * Cn + lane]      = o[ri][0];
            out[m * Cn + lane + 32] = o[ri][1];
        }
    }
}

// ---------------- launch ----------------
extern "C" void kernel_launch(void* const* d_in, const int* in_sizes, int n_in,
                              void* d_out, int out_size) {
    // input order: x, lengths, [out_lengths], W_ih, W_hh, b_ih, b_hh, W1, b1, W2, b2
    const int off = (n_in >= 11) ? 3 : 2;
    const float* x       = (const float*)d_in[0];
    const int*   lengths = (const int*)  d_in[1];
    const float* W_ih    = (const float*)d_in[off + 0];
    const float* W_hh    = (const float*)d_in[off + 1];
    const float* b_ih    = (const float*)d_in[off + 2];
    const float* b_hh    = (const float*)d_in[off + 3];
    const float* W1      = (const float*)d_in[off + 4];
    const float* b1      = (const float*)d_in[off + 5];
    const float* W2      = (const float*)d_in[off + 6];
    const float* b2      = (const float*)d_in[off + 7];
    float*       out     = (float*)d_out;

    const size_t smem1 = (size_t)(2 * ABUF + 2 * PBUF) * sizeof(float) + 16;  // ~53.8 KB
    const size_t smem2 = (size_t)2 * 32 * Hn * sizeof(float);                 // 64 KB

    cudaFuncSetAttribute(lstm_persistent,
                         cudaFuncAttributeMaxDynamicSharedMemorySize, (int)smem1);
    cudaFuncSetAttribute(mlp_epilogue,
                         cudaFuncAttributeMaxDynamicSharedMemorySize, (int)smem2);

    lstm_persistent<<<NCTA, NTHR, smem1>>>(x, lengths, W_ih, W_hh, b_ih, b_hh);
    mlp_epilogue<<<(Bn * OUTL) / 32, 256, smem2>>>(W1, b1, W2, b2, out);
}

// round 12
// speedup vs baseline: 5.6514x; 1.0001x over previous
#include <cuda_runtime.h>
#include <cstdint>
#include <cstddef>

// Problem constants (fixed shapes)
#define Tn    1024
#define Bn    128
#define In    64
#define Hn    256
#define Cn    64
#define OUTL  128
#define NCTA  128
#define NTHR  256
#define GRP   8              // CTAs per exchange group
#define NGRP  16             // 128/8
#define RB    8              // batch rows per group
#define GC    128            // gate-cols per CTA
#define HCPC  32             // h-cols per CTA
#define ASTR  328            // activation row stride (floats), 16B multiple
#define ABUF  (RB * ASTR)    // one activation buffer (floats)
#define PBUF  (RB * 4 * GC)  // one partials buffer (floats)

typedef unsigned long long ull;

// ---------------- persistent device state ----------------
__device__ float g_h[2][NGRP][RB][Hn];       // double-buffered hidden state (h_t -> buf t&1)
__device__ float g_decH[Bn][OUTL][Hn];       // decoder hidden states for epilogue

struct alignas(32) Flag { unsigned v; unsigned pad[7]; };
__device__ Flag g_flag[NGRP][GRP];           // per-producer counter: +1 per warp per step

// ---------------- helpers ----------------
__device__ __forceinline__ unsigned ld_acq_u32(const unsigned* p) {
    unsigned v;
    asm volatile("ld.acquire.gpu.global.u32 %0, [%1];" : "=r"(v) : "l"(p) : "memory");
    return v;
}
__device__ __forceinline__ void rel_add1(unsigned* p) {
    asm volatile("red.release.gpu.global.add.u32 [%0], %1;" :: "l"(p), "r"(1u) : "memory");
}
__device__ __forceinline__ ull pk2(float x, float y) {
    ull r; asm("mov.b64 %0, {%1, %2};" : "=l"(r) : "f"(x), "f"(y)); return r;
}
__device__ __forceinline__ void upk2(ull v, float& x, float& y) {
    asm("mov.b64 {%0, %1}, %2;" : "=f"(x), "=f"(y) : "l"(v));
}
__device__ __forceinline__ ull ffma2(ull a, ull b, ull c) {
    ull d; asm("fma.rn.f32x2 %0, %1, %2, %3;" : "=l"(d) : "l"(a), "l"(b), "l"(c));
    return d;
}
__device__ __forceinline__ float sigf(float x) {
    return 1.0f / (1.0f + __expf(-x));
}
__device__ __forceinline__ float tanhf_fast(float x) {
    x = fminf(fmaxf(x, -15.0f), 15.0f);
    float e = __expf(2.0f * x);
    return (e - 1.0f) / (e + 1.0f);
}

// x-phase: partials over x[16kq,16kq+16) into sx[16] register array.
__device__ __forceinline__ void gemm_x(const float* __restrict__ aS,
                                       float* __restrict__ sx,
                                       const ull* __restrict__ wr, int kq)
{
    const int xoff = 16 * kq;
    #pragma unroll
    for (int rp = 0; rp < 4; ++rp) {
        const float* b0 = aS + (2 * rp) * ASTR + xoff;
        const float* b1 = b0 + ASTR;
        ull a00 = 0ull, a01 = 0ull, a10 = 0ull, a11 = 0ull;
        #pragma unroll
        for (int u = 0; u < 4; ++u) {
            ulonglong2 A0 = *(const ulonglong2*)(b0 + 4 * u);
            a00 = ffma2(A0.x, wr[4 * u + 0], a00);
            a00 = ffma2(A0.y, wr[4 * u + 1], a00);
            a01 = ffma2(A0.x, wr[4 * u + 2], a01);
            a01 = ffma2(A0.y, wr[4 * u + 3], a01);
            ulonglong2 A1 = *(const ulonglong2*)(b1 + 4 * u);
            a10 = ffma2(A1.x, wr[4 * u + 0], a10);
            a10 = ffma2(A1.y, wr[4 * u + 1], a10);
            a11 = ffma2(A1.x, wr[4 * u + 2], a11);
            a11 = ffma2(A1.y, wr[4 * u + 3], a11);
        }
        float lo, hi;
        upk2(a00, lo, hi); sx[4 * rp + 0] = lo + hi;
        upk2(a01, lo, hi); sx[4 * rp + 1] = lo + hi;
        upk2(a10, lo, hi); sx[4 * rp + 2] = lo + hi;
        upk2(a11, lo, hi); sx[4 * rp + 3] = lo + hi;
    }
}

// h-phase: accumulate h[64kq,64kq+64), optionally seeded with x partials; store to part.
template<bool WITHSX>
__device__ __forceinline__ void gemm_h(const float* __restrict__ aS,
                                       float* __restrict__ part,
                                       const float* __restrict__ sx,
                                       const ull* __restrict__ wr,
                                       int kq, int cp)
{
    const int hoff = In + 64 * kq;
    #pragma unroll
    for (int rp = 0; rp < 4; ++rp) {
        const float* b0 = aS + (2 * rp) * ASTR + hoff;
        const float* b1 = b0 + ASTR;
        ull a00, a01, a10, a11;
        if (WITHSX) {
            a00 = pk2(sx[4 * rp + 0], 0.f);
            a01 = pk2(sx[4 * rp + 1], 0.f);
            a10 = pk2(sx[4 * rp + 2], 0.f);
            a11 = pk2(sx[4 * rp + 3], 0.f);
        } else {
            a00 = a01 = a10 = a11 = 0ull;
        }
        #pragma unroll
        for (int u = 0; u < 16; ++u) {
            const ull* wp = wr + 16 + 4 * u;
            ulonglong2 A0 = *(const ulonglong2*)(b0 + 4 * u);
            a00 = ffma2(A0.x, wp[0], a00);
            a00 = ffma2(A0.y, wp[1], a00);
            a01 = ffma2(A0.x, wp[2], a01);
            a01 = ffma2(A0.y, wp[3], a01);
            ulonglong2 A1 = *(const ulonglong2*)(b1 + 4 * u);
            a10 = ffma2(A1.x, wp[0], a10);
            a10 = ffma2(A1.y, wp[1], a10);
            a11 = ffma2(A1.x, wp[2], a11);
            a11 = ffma2(A1.y, wp[3], a11);
        }
        float lo, hi, s00, s01, s10, s11;
        upk2(a00, lo, hi); s00 = lo + hi;
        upk2(a01, lo, hi); s01 = lo + hi;
        upk2(a10, lo, hi); s10 = lo + hi;
        upk2(a11, lo, hi); s11 = lo + hi;
        *(float2*)(part + ((2 * rp + 0) * 4 + kq) * GC + 2 * cp) = make_float2(s00, s01);
        *(float2*)(part + ((2 * rp + 1) * 4 + kq) * GC + 2 * cp) = make_float2(s10, s11);
    }
}

// ---------------- persistent encoder + decoder kernel ----------------
extern "C" __global__ void __launch_bounds__(NTHR, 1)
lstm_persistent(const float* __restrict__ x, const int* __restrict__ lengths,
                const float* __restrict__ W_ih, const float* __restrict__ W_hh,
                const float* __restrict__ b_ih, const float* __restrict__ b_hh)
{
    extern __shared__ float sm[];
    float* smA = sm;                       // [2][RB][ASTR] activations [x_t | h_t]
    float* smP = sm + 2 * ABUF;            // [2][RB][4][GC] K-quarter partials
    unsigned* sbase = (unsigned*)(smP + 2 * PBUF);

    const int tid  = threadIdx.x;
    const int lane = tid & 31;
    const int wid  = tid >> 5;             // warp 0..7: stages slab 'wid', updates row 'wid'
    const int grp  = blockIdx.x >> 3;      // group 0..15
    const int rank = blockIdx.x & 7;       // rank in group 0..7
    const int row0 = grp * RB;

    // GEMM role: col-pair + K-quarter (pair of warps {2kq, 2kq+1})
    const int cp = tid & 63;
    const int kq = tid >> 6;
    const int c0 = cp * 2, c1 = cp * 2 + 1;

    // ---- weights into registers (once): wr[0..15]=x-units, wr[16..79]=h-units ----
    ull wr[80];
    {
        const int grow0 = (c0 >> 5) * Hn + rank * HCPC + (c0 & 31);
        const int grow1 = (c1 >> 5) * Hn + rank * HCPC + (c1 & 31);
        #pragma unroll
        for (int u = 0; u < 4; ++u) {
            float w0[4], w1[4];
            #pragma unroll
            for (int j = 0; j < 4; ++j) {
                int kk = 16 * kq + 4 * u + j;
                w0[j] = W_ih[(size_t)grow0 * In + kk];
                w1[j] = W_ih[(size_t)grow1 * In + kk];
            }
            wr[4 * u + 0] = pk2(w0[0], w0[1]);
            wr[4 * u + 1] = pk2(w0[2], w0[3]);
            wr[4 * u + 2] = pk2(w1[0], w1[1]);
            wr[4 * u + 3] = pk2(w1[2], w1[3]);
        }
        #pragma unroll
        for (int u = 0; u < 16; ++u) {
            float w0[4], w1[4];
            #pragma unroll
            for (int j = 0; j < 4; ++j) {
                int kk = 64 * kq + 4 * u + j;
                w0[j] = W_hh[(size_t)grow0 * Hn + kk];
                w1[j] = W_hh[(size_t)grow1 * Hn + kk];
            }
            wr[16 + 4 * u + 0] = pk2(w0[0], w0[1]);
            wr[16 + 4 * u + 1] = pk2(w0[2], w0[3]);
            wr[16 + 4 * u + 2] = pk2(w1[0], w1[1]);
            wr[16 + 4 * u + 3] = pk2(w1[2], w1[3]);
        }
    }

    // update role: warp wid owns row wid, lane owns local h-col
    float bq0, bq1, bq2, bq3;
    {
        int c = rank * HCPC + lane;
        bq0 = b_ih[0 * Hn + c] + b_hh[0 * Hn + c];
        bq1 = b_ih[1 * Hn + c] + b_hh[1 * Hn + c];
        bq2 = b_ih[2 * Hn + c] + b_hh[2 * Hn + c];
        bq3 = b_ih[3 * Hn + c] + b_hh[3 * Hn + c];
    }
    const int ulen = lengths[row0 + wid];
    float creg = 0.0f;

    // ---- init: snapshot base, zero own h0 slab row, stage x_0 into buffer 0 ----
    if (tid == 0) *sbase = ld_acq_u32(&g_flag[grp][rank].v);
    if (lane < 8)                                   // warp wid zeroes row wid of own slab
        *(((float4*)&g_h[0][grp][wid][rank * HCPC]) + lane) = make_float4(0.f, 0.f, 0.f, 0.f);
    if ((wid & 1) == 0) {                           // even warp of pair kq stages its x slice
        int r = lane >> 2, c4 = lane & 3;
        float4 v = *(((const float4*)(x + ((size_t)(row0 + r) * Tn) * In)) + 4 * kq + c4);
        *(((float4*)(smA + r * ASTR)) + 4 * kq + c4) = v;
    }
    __syncthreads();
    const unsigned base = *sbase;
    if (lane == 0) rel_add1(&g_flag[grp][rank].v);  // 8 warps -> +8: h_0 published

    // ================= encoder: 1024 steps =================
    for (int t = 0; t < Tn; ++t) {
        float* aCur = smA + (t & 1) * ABUF;
        float* aNxt = smA + ((t + 1) & 1) * ABUF;
        float* pCur = smP + (t & 1) * PBUF;

        // (a) x-phase (no h dependency; hides peers' publish latency)
        float sx[16];
        gemm_x(aCur, sx, wr, kq);

        // (b) poll ONLY own slab's producer, stage slab 'wid' into aCur
        if (lane == 0) {
            const unsigned* fp = &g_flag[grp][wid].v;
            const unsigned tgt = base + 8u * (unsigned)(t + 1);
            while ((int)(ld_acq_u32(fp) - tgt) < 0) { }
        }
        __syncwarp();
        {
            const float* src = &g_h[t & 1][grp][0][wid * HCPC];
            float*       dst = aCur + In + wid * HCPC;
            #pragma unroll
            for (int j = 0; j < 2; ++j) {
                int idx = lane + 32 * j, r = idx >> 3, c4 = idx & 7;
                float4 v = __ldcg(((const float4*)(src + (size_t)r * Hn)) + c4);
                *(((float4*)(dst + r * ASTR)) + c4) = v;
            }
        }
        asm volatile("bar.sync %0, 64;" :: "r"(kq + 1) : "memory");  // pair: both slabs staged

        // x_{t+1} prefetch to regs (DRAM latency hidden under h-phase)
        float4 xv;
        const bool dox = ((wid & 1) == 0) && (t + 1 < Tn);
        if (dox) {
            int r = lane >> 2, c4 = lane & 3;
            xv = *(((const float4*)(x + ((size_t)(row0 + r) * Tn + t + 1) * In)) + 4 * kq + c4);
        }

        // (c) h-phase, seeded by x partials
        gemm_h<true>(aCur, pCur, sx, wr, kq, cp);
        if (dox) {
            int r = lane >> 2, c4 = lane & 3;
            *(((float4*)(aNxt + r * ASTR)) + 4 * kq + c4) = xv;
        }
        __syncthreads();                                             // the ONE CTA sync

        // (e) reduce + cell update for (row wid, hcol lane)
        {
            float g0 = bq0, g1 = bq1, g2 = bq2, g3 = bq3;
            #pragma unroll
            for (int k4 = 0; k4 < 4; ++k4) {
                const float* pr = pCur + (wid * 4 + k4) * GC + lane;
                g0 += pr[0]; g1 += pr[32]; g2 += pr[64]; g3 += pr[96];
            }
            float c2 = sigf(g1) * creg + sigf(g0) * tanhf_fast(g2);
            float h2 = sigf(g3) * tanhf_fast(c2);
            if (t >= ulen) {                                         // freeze masked rows
                h2 = aCur[wid * ASTR + In + rank * HCPC + lane];
                c2 = creg;
            }
            creg = c2;
            __stcg(&g_h[(t + 1) & 1][grp][wid][rank * HCPC + lane], h2);
        }
        __syncwarp();
        if (lane == 0) rel_add1(&g_flag[grp][rank].v);               // per-warp publish
    }

    // ================= decoder: 128 steps (gates_x = bias) =================
    for (int s = 0; s < OUTL; ++s) {
        const int u = Tn + s;
        float* aCur = smA + (u & 1) * ABUF;
        float* pCur = smP + (u & 1) * PBUF;

        if (lane == 0) {
            const unsigned* fp = &g_flag[grp][wid].v;
            const unsigned tgt = base + 8u * (unsigned)(u + 1);
            while ((int)(ld_acq_u32(fp) - tgt) < 0) { }
        }
        __syncwarp();
        {
            const float* src = &g_h[u & 1][grp][0][wid * HCPC];
            float*       dst = aCur + In + wid * HCPC;
            #pragma unroll
            for (int j = 0; j < 2; ++j) {
                int idx = lane + 32 * j, r = idx >> 3, c4 = idx & 7;
                float4 v = __ldcg(((const float4*)(src + (size_t)r * Hn)) + c4);
                *(((float4*)(dst + r * ASTR)) + c4) = v;
            }
        }
        asm volatile("bar.sync %0, 64;" :: "r"(kq + 1) : "memory");

        gemm_h<false>(aCur, pCur, (const float*)nullptr, wr, kq, cp);
        __syncthreads();

        {
            float g0 = bq0, g1 = bq1, g2 = bq2, g3 = bq3;
            #pragma unroll
            for (int k4 = 0; k4 < 4; ++k4) {
                const float* pr = pCur + (wid * 4 + k4) * GC + lane;
                g0 += pr[0]; g1 += pr[32]; g2 += pr[64]; g3 += pr[96];
            }
            float c2 = sigf(g1) * creg + sigf(g0) * tanhf_fast(g2);
            float h2 = sigf(g3) * tanhf_fast(c2);
            creg = c2;
            __stcg(&g_h[(u + 1) & 1][grp][wid][rank * HCPC + lane], h2);
            g_decH[row0 + wid][s][rank * HCPC + lane] = h2;          // for epilogue MLP
        }
        if (s + 1 < OUTL) {
            __syncwarp();
            if (lane == 0) rel_add1(&g_flag[grp][rank].v);
        }
    }
}

// ---------------- epilogue: out = relu(decH @ W1^T + b1) @ W2^T + b2 ----------------
extern "C" __global__ void __launch_bounds__(256, 1)
mlp_epilogue(const float* __restrict__ W1, const float* __restrict__ b1,
             const float* __restrict__ W2, const float* __restrict__ b2,
             float* __restrict__ out)
{
    extern __shared__ float sm[];
    float* As = sm;            // [32][256] decoder h tile
    float* Hs = sm + 32 * 256; // [32][256] relu hidden tile

    const int tid  = threadIdx.x;
    const int lane = tid & 31;
    const int w    = tid >> 5;
    const int m0   = blockIdx.x * 32;

    const float* dh = &g_decH[0][0][0];
    for (int idx = tid; idx < 32 * (Hn / 4); idx += 256) {
        int r = idx >> 6, c4 = idx & 63;
        *(((float4*)(As + r * Hn)) + c4) =
            *(((const float4*)(dh + (size_t)(m0 + r) * Hn)) + c4);
    }
    __syncthreads();

    {
        const int h = w * 32 + lane;
        float acc[32];
        const float bv = b1[h];
        #pragma unroll
        for (int r = 0; r < 32; ++r) acc[r] = bv;
        for (int k = 0; k < Hn; k += 4) {
            float4 wv = *(const float4*)(W1 + (size_t)h * Hn + k);
            #pragma unroll
            for (int r = 0; r < 32; ++r) {
                float4 av = *(const float4*)(As + r * Hn + k);
                acc[r] = fmaf(av.x, wv.x, fmaf(av.y, wv.y,
                         fmaf(av.z, wv.z, fmaf(av.w, wv.w, acc[r]))));
            }
        }
        #pragma unroll
        for (int r = 0; r < 32; ++r) Hs[r * Hn + h] = fmaxf(acc[r], 0.0f);
    }
    __syncthreads();

    {
        float o[4][2];
        const float ba = b2[lane];
        const float bb = b2[lane + 32];
        #pragma unroll
        for (int ri = 0; ri < 4; ++ri) { o[ri][0] = ba; o[ri][1] = bb; }
        for (int k = 0; k < Hn; k += 4) {
            float4 wa = *(const float4*)(W2 + (size_t)lane * Hn + k);
            float4 wb = *(const float4*)(W2 + (size_t)(lane + 32) * Hn + k);
            #pragma unroll
            for (int ri = 0; ri < 4; ++ri) {
                float4 hv = *(const float4*)(Hs + (w * 4 + ri) * Hn + k);
                o[ri][0] = fmaf(hv.x, wa.x, fmaf(hv.y, wa.y,
                           fmaf(hv.z, wa.z, fmaf(hv.w, wa.w, o[ri][0]))));
                o[ri][1] = fmaf(hv.x, wb.x, fmaf(hv.y, wb.y,
                           fmaf(hv.z, wb.z, fmaf(hv.w, wb.w, o[ri][1]))));
            }
        }
        #pragma unroll
        for (int ri = 0; ri < 4; ++ri) {
            size_t m = (size_t)(m0 + w * 4 + ri);
            out[m * Cn + lane]      = o[ri][0];
            out[m * Cn + lane + 32] = o[ri][1];
        }
    }
}

// ---------------- launch ----------------
extern "C" void kernel_launch(void* const* d_in, const int* in_sizes, int n_in,
                              void* d_out, int out_size) {
    // input order: x, lengths, [out_lengths], W_ih, W_hh, b_ih, b_hh, W1, b1, W2, b2
    const int off = (n_in >= 11) ? 3 : 2;
    const float* x       = (const float*)d_in[0];
    const int*   lengths = (const int*)  d_in[1];
    const float* W_ih    = (const float*)d_in[off + 0];
    const float* W_hh    = (const float*)d_in[off + 1];
    const float* b_ih    = (const float*)d_in[off + 2];
    const float* b_hh    = (const float*)d_in[off + 3];
    const float* W1      = (const float*)d_in[off + 4];
    const float* b1      = (const float*)d_in[off + 5];
    const float* W2      = (const float*)d_in[off + 6];
    const float* b2      = (const float*)d_in[off + 7];
    float*       out     = (float*)d_out;

    const size_t smem1 = (size_t)(2 * ABUF + 2 * PBUF) * sizeof(float) + 16;  // ~53.8 KB
    const size_t smem2 = (size_t)2 * 32 * Hn * sizeof(float);                 // 64 KB

    cudaFuncSetAttribute(lstm_persistent,
                         cudaFuncAttributeMaxDynamicSharedMemorySize, (int)smem1);
    cudaFuncSetAttribute(mlp_epilogue,
                         cudaFuncAttributeMaxDynamicSharedMemorySize, (int)smem2);

    lstm_persistent<<<NCTA, NTHR, smem1>>>(x, lengths, W_ih, W_hh, b_ih, b_hh);
    mlp_epilogue<<<(Bn * OUTL) / 32, 256, smem2>>>(W1, b1, W2, b2, out);
}

// round 13
// speedup vs baseline: 5.6528x; 1.0003x over previous
#include <cuda_runtime.h>
#include <cstdint>
#include <cstddef>

// Problem constants (fixed shapes)
#define Tn    1024
#define Bn    128
#define In    64
#define Hn    256
#define Cn    64
#define OUTL  128
#define NCTA  128
#define NTHR  256
#define GRP   8              // CTAs per exchange group
#define NGRP  16             // 128/8
#define RB    8              // batch rows per group
#define GC    128            // gate-cols per CTA
#define HCPC  32             // h-cols per CTA
#define ASTR  328            // activation row stride (floats), 16B multiple
#define ABUF  (RB * ASTR)    // one activation buffer (floats)
#define PBUF  (RB * 4 * GC)  // one partials buffer (floats)

typedef unsigned long long ull;

// ---------------- persistent device state ----------------
__device__ float g_h[2][NGRP][RB][Hn];       // double-buffered hidden state (h_t -> buf t&1)
__device__ float g_decH[Bn][OUTL][Hn];       // decoder hidden states for epilogue

struct alignas(32) Flag { unsigned v; unsigned pad[7]; };
__device__ Flag g_flag[NGRP][GRP];           // per-producer counter: +1 per warp per step

// ---------------- helpers ----------------
__device__ __forceinline__ unsigned ld_acq_u32(const unsigned* p) {
    unsigned v;
    asm volatile("ld.acquire.gpu.global.u32 %0, [%1];" : "=r"(v) : "l"(p) : "memory");
    return v;
}
__device__ __forceinline__ void rel_add1(unsigned* p) {
    asm volatile("red.release.gpu.global.add.u32 [%0], %1;" :: "l"(p), "r"(1u) : "memory");
}
__device__ __forceinline__ ull pk2(float x, float y) {
    ull r; asm("mov.b64 %0, {%1, %2};" : "=l"(r) : "f"(x), "f"(y)); return r;
}
__device__ __forceinline__ void upk2(ull v, float& x, float& y) {
    asm("mov.b64 {%0, %1}, %2;" : "=f"(x), "=f"(y) : "l"(v));
}
__device__ __forceinline__ ull ffma2(ull a, ull b, ull c) {
    ull d; asm("fma.rn.f32x2 %0, %1, %2, %3;" : "=l"(d) : "l"(a), "l"(b), "l"(c));
    return d;
}
__device__ __forceinline__ float sigf(float x) {
    return 1.0f / (1.0f + __expf(-x));
}
__device__ __forceinline__ float tanhf_fast(float x) {
    x = fminf(fmaxf(x, -15.0f), 15.0f);
    float e = __expf(2.0f * x);
    return (e - 1.0f) / (e + 1.0f);
}

// x-phase: partials over x[16kq,16kq+16) into sx[16] register array.
__device__ __forceinline__ void gemm_x(const float* __restrict__ aS,
                                       float* __restrict__ sx,
                                       const ull* __restrict__ wr, int kq)
{
    const int xoff = 16 * kq;
    #pragma unroll
    for (int rp = 0; rp < 4; ++rp) {
        const float* b0 = aS + (2 * rp) * ASTR + xoff;
        const float* b1 = b0 + ASTR;
        ull a00 = 0ull, a01 = 0ull, a10 = 0ull, a11 = 0ull;
        #pragma unroll
        for (int u = 0; u < 4; ++u) {
            ulonglong2 A0 = *(const ulonglong2*)(b0 + 4 * u);
            a00 = ffma2(A0.x, wr[4 * u + 0], a00);
            a00 = ffma2(A0.y, wr[4 * u + 1], a00);
            a01 = ffma2(A0.x, wr[4 * u + 2], a01);
            a01 = ffma2(A0.y, wr[4 * u + 3], a01);
            ulonglong2 A1 = *(const ulonglong2*)(b1 + 4 * u);
            a10 = ffma2(A1.x, wr[4 * u + 0], a10);
            a10 = ffma2(A1.y, wr[4 * u + 1], a10);
            a11 = ffma2(A1.x, wr[4 * u + 2], a11);
            a11 = ffma2(A1.y, wr[4 * u + 3], a11);
        }
        float lo, hi;
        upk2(a00, lo, hi); sx[4 * rp + 0] = lo + hi;
        upk2(a01, lo, hi); sx[4 * rp + 1] = lo + hi;
        upk2(a10, lo, hi); sx[4 * rp + 2] = lo + hi;
        upk2(a11, lo, hi); sx[4 * rp + 3] = lo + hi;
    }
}

// h-phase: accumulate h[64kq,64kq+64), optionally seeded with x partials; store to part.
template<bool WITHSX>
__device__ __forceinline__ void gemm_h(const float* __restrict__ aS,
                                       float* __restrict__ part,
                                       const float* __restrict__ sx,
                                       const ull* __restrict__ wr,
                                       int kq, int cp)
{
    const int hoff = In + 64 * kq;
    #pragma unroll
    for (int rp = 0; rp < 4; ++rp) {
        const float* b0 = aS + (2 * rp) * ASTR + hoff;
        const float* b1 = b0 + ASTR;
        ull a00, a01, a10, a11;
        if (WITHSX) {
            a00 = pk2(sx[4 * rp + 0], 0.f);
            a01 = pk2(sx[4 * rp + 1], 0.f);
            a10 = pk2(sx[4 * rp + 2], 0.f);
            a11 = pk2(sx[4 * rp + 3], 0.f);
        } else {
            a00 = a01 = a10 = a11 = 0ull;
        }
        #pragma unroll
        for (int u = 0; u < 16; ++u) {
            const ull* wp = wr + 16 + 4 * u;
            ulonglong2 A0 = *(const ulonglong2*)(b0 + 4 * u);
            a00 = ffma2(A0.x, wp[0], a00);
            a00 = ffma2(A0.y, wp[1], a00);
            a01 = ffma2(A0.x, wp[2], a01);
            a01 = ffma2(A0.y, wp[3], a01);
            ulonglong2 A1 = *(const ulonglong2*)(b1 + 4 * u);
            a10 = ffma2(A1.x, wp[0], a10);
            a10 = ffma2(A1.y, wp[1], a10);
            a11 = ffma2(A1.x, wp[2], a11);
            a11 = ffma2(A1.y, wp[3], a11);
        }
        float lo, hi, s00, s01, s10, s11;
        upk2(a00, lo, hi); s00 = lo + hi;
        upk2(a01, lo, hi); s01 = lo + hi;
        upk2(a10, lo, hi); s10 = lo + hi;
        upk2(a11, lo, hi); s11 = lo + hi;
        *(float2*)(part + ((2 * rp + 0) * 4 + kq) * GC + 2 * cp) = make_float2(s00, s01);
        *(float2*)(part + ((2 * rp + 1) * 4 + kq) * GC + 2 * cp) = make_float2(s10, s11);
    }
}

// ---------------- persistent encoder + decoder kernel ----------------
extern "C" __global__ void __launch_bounds__(NTHR, 1)
lstm_persistent(const float* __restrict__ x, const int* __restrict__ lengths,
                const float* __restrict__ W_ih, const float* __restrict__ W_hh,
                const float* __restrict__ b_ih, const float* __restrict__ b_hh)
{
    extern __shared__ float sm[];
    float* smA = sm;                       // [2][RB][ASTR] activations [x_t | h_t]
    float* smP = sm + 2 * ABUF;            // [2][RB][4][GC] K-quarter partials
    unsigned* sbase = (unsigned*)(smP + 2 * PBUF);

    const int tid  = threadIdx.x;
    const int lane = tid & 31;
    const int wid  = tid >> 5;             // warp 0..7: stages slab 'wid', updates row 'wid'
    const int grp  = blockIdx.x >> 3;      // group 0..15
    const int rank = blockIdx.x & 7;       // rank in group 0..7
    const int row0 = grp * RB;

    // GEMM role: col-pair + K-quarter (pair of warps {2kq, 2kq+1})
    const int cp = tid & 63;
    const int kq = tid >> 6;
    const int c0 = cp * 2, c1 = cp * 2 + 1;

    // ---- weights into registers (once): wr[0..15]=x-units, wr[16..79]=h-units ----
    ull wr[80];
    {
        const int grow0 = (c0 >> 5) * Hn + rank * HCPC + (c0 & 31);
        const int grow1 = (c1 >> 5) * Hn + rank * HCPC + (c1 & 31);
        #pragma unroll
        for (int u = 0; u < 4; ++u) {
            float w0[4], w1[4];
            #pragma unroll
            for (int j = 0; j < 4; ++j) {
                int kk = 16 * kq + 4 * u + j;
                w0[j] = W_ih[(size_t)grow0 * In + kk];
                w1[j] = W_ih[(size_t)grow1 * In + kk];
            }
            wr[4 * u + 0] = pk2(w0[0], w0[1]);
            wr[4 * u + 1] = pk2(w0[2], w0[3]);
            wr[4 * u + 2] = pk2(w1[0], w1[1]);
            wr[4 * u + 3] = pk2(w1[2], w1[3]);
        }
        #pragma unroll
        for (int u = 0; u < 16; ++u) {
            float w0[4], w1[4];
            #pragma unroll
            for (int j = 0; j < 4; ++j) {
                int kk = 64 * kq + 4 * u + j;
                w0[j] = W_hh[(size_t)grow0 * Hn + kk];
                w1[j] = W_hh[(size_t)grow1 * Hn + kk];
            }
            wr[16 + 4 * u + 0] = pk2(w0[0], w0[1]);
            wr[16 + 4 * u + 1] = pk2(w0[2], w0[3]);
            wr[16 + 4 * u + 2] = pk2(w1[0], w1[1]);
            wr[16 + 4 * u + 3] = pk2(w1[2], w1[3]);
        }
    }

    // update role: warp wid owns row wid, lane owns local h-col
    float bq0, bq1, bq2, bq3;
    {
        int c = rank * HCPC + lane;
        bq0 = b_ih[0 * Hn + c] + b_hh[0 * Hn + c];
        bq1 = b_ih[1 * Hn + c] + b_hh[1 * Hn + c];
        bq2 = b_ih[2 * Hn + c] + b_hh[2 * Hn + c];
        bq3 = b_ih[3 * Hn + c] + b_hh[3 * Hn + c];
    }
    const int ulen = lengths[row0 + wid];
    float creg = 0.0f;

    // ---- init: snapshot base, zero own h0 slab row, stage x_0 into buffer 0 ----
    if (tid == 0) *sbase = ld_acq_u32(&g_flag[grp][rank].v);
    if (lane < 8)                                   // warp wid zeroes row wid of own slab
        *(((float4*)&g_h[0][grp][wid][rank * HCPC]) + lane) = make_float4(0.f, 0.f, 0.f, 0.f);
    if ((wid & 1) == 0) {                           // even warp of pair kq stages its x slice
        int r = lane >> 2, c4 = lane & 3;
        float4 v = *(((const float4*)(x + ((size_t)(row0 + r) * Tn) * In)) + 4 * kq + c4);
        *(((float4*)(smA + r * ASTR)) + 4 * kq + c4) = v;
    }
    __syncthreads();
    const unsigned base = *sbase;
    if (lane == 0) rel_add1(&g_flag[grp][rank].v);  // 8 warps -> +8: h_0 published

    // ================= encoder: 1024 steps =================
    for (int t = 0; t < Tn; ++t) {
        float* aCur = smA + (t & 1) * ABUF;
        float* aNxt = smA + ((t + 1) & 1) * ABUF;
        float* pCur = smP + (t & 1) * PBUF;

        // (a) x-phase (no h dependency; hides peers' publish latency)
        float sx[16];
        gemm_x(aCur, sx, wr, kq);

        // (b) poll ONLY own slab's producer, stage slab 'wid' into aCur
        if (lane == 0) {
            const unsigned* fp = &g_flag[grp][wid].v;
            const unsigned tgt = base + 8u * (unsigned)(t + 1);
            while ((int)(ld_acq_u32(fp) - tgt) < 0) { }
        }
        __syncwarp();
        {
            const float* src = &g_h[t & 1][grp][0][wid * HCPC];
            float*       dst = aCur + In + wid * HCPC;
            #pragma unroll
            for (int j = 0; j < 2; ++j) {
                int idx = lane + 32 * j, r = idx >> 3, c4 = idx & 7;
                float4 v = __ldcg(((const float4*)(src + (size_t)r * Hn)) + c4);
                *(((float4*)(dst + r * ASTR)) + c4) = v;
            }
        }
        asm volatile("bar.sync %0, 64;" :: "r"(kq + 1) : "memory");  // pair: both slabs staged

        // x_{t+1} prefetch to regs (DRAM latency hidden under h-phase)
        float4 xv;
        const bool dox = ((wid & 1) == 0) && (t + 1 < Tn);
        if (dox) {
            int r = lane >> 2, c4 = lane & 3;
            xv = *(((const float4*)(x + ((size_t)(row0 + r) * Tn + t + 1) * In)) + 4 * kq + c4);
        }

        // (c) h-phase, seeded by x partials
        gemm_h<true>(aCur, pCur, sx, wr, kq, cp);
        if (dox) {
            int r = lane >> 2, c4 = lane & 3;
            *(((float4*)(aNxt + r * ASTR)) + 4 * kq + c4) = xv;
        }
        __syncthreads();                                             // the ONE CTA sync

        // (e) reduce + cell update for (row wid, hcol lane)
        {
            float g0 = bq0, g1 = bq1, g2 = bq2, g3 = bq3;
            #pragma unroll
            for (int k4 = 0; k4 < 4; ++k4) {
                const float* pr = pCur + (wid * 4 + k4) * GC + lane;
                g0 += pr[0]; g1 += pr[32]; g2 += pr[64]; g3 += pr[96];
            }
            float c2 = sigf(g1) * creg + sigf(g0) * tanhf_fast(g2);
            float h2 = sigf(g3) * tanhf_fast(c2);
            if (t >= ulen) {                                         // freeze masked rows
                h2 = aCur[wid * ASTR + In + rank * HCPC + lane];
                c2 = creg;
            }
            creg = c2;
            __stcg(&g_h[(t + 1) & 1][grp][wid][rank * HCPC + lane], h2);
        }
        __syncwarp();
        if (lane == 0) rel_add1(&g_flag[grp][rank].v);               // per-warp publish
    }

    // ================= decoder: 128 steps (gates_x = bias) =================
    for (int s = 0; s < OUTL; ++s) {
        const int u = Tn + s;
        float* aCur = smA + (u & 1) * ABUF;
        float* pCur = smP + (u & 1) * PBUF;

        if (lane == 0) {
            const unsigned* fp = &g_flag[grp][wid].v;
            const unsigned tgt = base + 8u * (unsigned)(u + 1);
            while ((int)(ld_acq_u32(fp) - tgt) < 0) { }
        }
        __syncwarp();
        {
            const float* src = &g_h[u & 1][grp][0][wid * HCPC];
            float*       dst = aCur + In + wid * HCPC;
            #pragma unroll
            for (int j = 0; j < 2; ++j) {
                int idx = lane + 32 * j, r = idx >> 3, c4 = idx & 7;
                float4 v = __ldcg(((const float4*)(src + (size_t)r * Hn)) + c4);
                *(((float4*)(dst + r * ASTR)) + c4) = v;
            }
        }
        asm volatile("bar.sync %0, 64;" :: "r"(kq + 1) : "memory");

        gemm_h<false>(aCur, pCur, (const float*)nullptr, wr, kq, cp);
        __syncthreads();

        {
            float g0 = bq0, g1 = bq1, g2 = bq2, g3 = bq3;
            #pragma unroll
            for (int k4 = 0; k4 < 4; ++k4) {
                const float* pr = pCur + (wid * 4 + k4) * GC + lane;
                g0 += pr[0]; g1 += pr[32]; g2 += pr[64]; g3 += pr[96];
            }
            float c2 = sigf(g1) * creg + sigf(g0) * tanhf_fast(g2);
            float h2 = sigf(g3) * tanhf_fast(c2);
            creg = c2;
            __stcg(&g_h[(u + 1) & 1][grp][wid][rank * HCPC + lane], h2);
            g_decH[row0 + wid][s][rank * HCPC + lane] = h2;          // for epilogue MLP
        }
        if (s + 1 < OUTL) {
            __syncwarp();
            if (lane == 0) rel_add1(&g_flag[grp][rank].v);
        }
    }
}

// ---------------- epilogue: out = relu(decH @ W1^T + b1) @ W2^T + b2 ----------------
extern "C" __global__ void __launch_bounds__(256, 1)
mlp_epilogue(const float* __restrict__ W1, const float* __restrict__ b1,
             const float* __restrict__ W2, const float* __restrict__ b2,
             float* __restrict__ out)
{
    extern __shared__ float sm[];
    float* As = sm;            // [32][256] decoder h tile
    float* Hs = sm + 32 * 256; // [32][256] relu hidden tile

    const int tid  = threadIdx.x;
    const int lane = tid & 31;
    const int w    = tid >> 5;
    const int m0   = blockIdx.x * 32;

    const float* dh = &g_decH[0][0][0];
    for (int idx = tid; idx < 32 * (Hn / 4); idx += 256) {
        int r = idx >> 6, c4 = idx & 63;
        *(((float4*)(As + r * Hn)) + c4) =
            *(((const float4*)(dh + (size_t)(m0 + r) * Hn)) + c4);
    }
    __syncthreads();

    {
        const int h = w * 32 + lane;
        float acc[32];
        const float bv = b1[h];
        #pragma unroll
        for (int r = 0; r < 32; ++r) acc[r] = bv;
        for (int k = 0; k < Hn; k += 4) {
            float4 wv = *(const float4*)(W1 + (size_t)h * Hn + k);
            #pragma unroll
            for (int r = 0; r < 32; ++r) {
                float4 av = *(const float4*)(As + r * Hn + k);
                acc[r] = fmaf(av.x, wv.x, fmaf(av.y, wv.y,
                         fmaf(av.z, wv.z, fmaf(av.w, wv.w, acc[r]))));
            }
        }
        #pragma unroll
        for (int r = 0; r < 32; ++r) Hs[r * Hn + h] = fmaxf(acc[r], 0.0f);
    }
    __syncthreads();

    {
        float o[4][2];
        const float ba = b2[lane];
        const float bb = b2[lane + 32];
        #pragma unroll
        for (int ri = 0; ri < 4; ++ri) { o[ri][0] = ba; o[ri][1] = bb; }
        for (int k = 0; k < Hn; k += 4) {
            float4 wa = *(const float4*)(W2 + (size_t)lane * Hn + k);
            float4 wb = *(const float4*)(W2 + (size_t)(lane + 32) * Hn + k);
            #pragma unroll
            for (int ri = 0; ri < 4; ++ri) {
                float4 hv = *(const float4*)(Hs + (w * 4 + ri) * Hn + k);
                o[ri][0] = fmaf(hv.x, wa.x, fmaf(hv.y, wa.y,
                           fmaf(hv.z, wa.z, fmaf(hv.w, wa.w, o[ri][0]))));
                o[ri][1] = fmaf(hv.x, wb.x, fmaf(hv.y, wb.y,
                           fmaf(hv.z, wb.z, fmaf(hv.w, wb.w, o[ri][1]))));
            }
        }
        #pragma unroll
        for (int ri = 0; ri < 4; ++ri) {
            size_t m = (size_t)(m0 + w * 4 + ri);
            out[m * Cn + lane]      = o[ri][0];
            out[m * Cn + lane + 32] = o[ri][1];
        }
    }
}

// ---------------- launch ----------------
extern "C" void kernel_launch(void* const* d_in, const int* in_sizes, int n_in,
                              void* d_out, int out_size) {
    // input order: x, lengths, [out_lengths], W_ih, W_hh, b_ih, b_hh, W1, b1, W2, b2
    const int off = (n_in >= 11) ? 3 : 2;
    const float* x       = (const float*)d_in[0];
    const int*   lengths = (const int*)  d_in[1];
    const float* W_ih    = (const float*)d_in[off + 0];
    const float* W_hh    = (const float*)d_in[off + 1];
    const float* b_ih    = (const float*)d_in[off + 2];
    const float* b_hh    = (const float*)d_in[off + 3];
    const float* W1      = (const float*)d_in[off + 4];
    const float* b1      = (const float*)d_in[off + 5];
    const float* W2      = (const float*)d_in[off + 6];
    const float* b2      = (const float*)d_in[off + 7];
    float*       out     = (float*)d_out;

    const size_t smem1 = (size_t)(2 * ABUF + 2 * PBUF) * sizeof(float) + 16;  // ~53.8 KB
    const size_t smem2 = (size_t)2 * 32 * Hn * sizeof(float);                 // 64 KB

    cudaFuncSetAttribute(lstm_persistent,
                         cudaFuncAttributeMaxDynamicSharedMemorySize, (int)smem1);
    cudaFuncSetAttribute(mlp_epilogue,
                         cudaFuncAttributeMaxDynamicSharedMemorySize, (int)smem2);

    lstm_persistent<<<NCTA, NTHR, smem1>>>(x, lengths, W_ih, W_hh, b_ih, b_hh);
    mlp_epilogue<<<(Bn * OUTL) / 32, 256, smem2>>>(W1, b1, W2, b2, out);
}